// round 1
// baseline (speedup 1.0000x reference)
#include <cuda_runtime.h>
#include <cuda_bf16.h>
#include <math.h>

#define CCH 512
#define NPX 4096
#define GROUPS 32
#define CPG 16   // channels per group

// ---------------- scratch (static device memory; no allocs) ----------------
__device__ float g_h[(size_t)2 * CCH * NPX];   // normalized input  [B,C,N]
__device__ float g_q[(size_t)2 * CCH * NPX];
__device__ float g_k[(size_t)2 * CCH * NPX];
__device__ float g_v[(size_t)2 * CCH * NPX];
__device__ float g_o[(size_t)2 * CCH * NPX];
__device__ float g_s[(size_t)2 * NPX * NPX];   // scores / attn     [B,N,N]

// ---------------- GroupNorm ----------------
// one block per (b, g); 256 threads; single pass for sum/sumsq then normalize
__global__ void __launch_bounds__(256) gn_kernel(const float* __restrict__ x,
                                                 const float* __restrict__ gamma,
                                                 const float* __restrict__ beta,
                                                 float* __restrict__ h) {
    int b = blockIdx.x >> 5;
    int g = blockIdx.x & 31;
    const size_t base = ((size_t)b * CCH + (size_t)g * CPG) * NPX;
    const float4* xp = (const float4*)(x + base);
    const int TOT4 = CPG * NPX / 4;  // 16384
    int tid = threadIdx.x;

    float s = 0.f, ss = 0.f;
    for (int i = tid; i < TOT4; i += 256) {
        float4 v = xp[i];
        s  += v.x + v.y + v.z + v.w;
        ss += v.x * v.x + v.y * v.y + v.z * v.z + v.w * v.w;
    }
    // block reduce (8 warps)
    __shared__ float rs[8], rss[8];
    #pragma unroll
    for (int o = 16; o > 0; o >>= 1) {
        s  += __shfl_xor_sync(0xffffffffu, s, o);
        ss += __shfl_xor_sync(0xffffffffu, ss, o);
    }
    if ((tid & 31) == 0) { rs[tid >> 5] = s; rss[tid >> 5] = ss; }
    __syncthreads();
    float S = 0.f, SS = 0.f;
    #pragma unroll
    for (int w = 0; w < 8; w++) { S += rs[w]; SS += rss[w]; }

    const float inv_cnt = 1.0f / (float)(CPG * NPX);
    float mean = S * inv_cnt;
    float var  = SS * inv_cnt - mean * mean;
    float rstd = rsqrtf(var + 1e-6f);

    float4* hp = (float4*)(h + base);
    for (int i = tid; i < TOT4; i += 256) {
        int c = g * CPG + (i >> 10);          // i*4 / 4096
        float ga = gamma[c] * rstd;
        float be = beta[c] - mean * ga;
        float4 v = xp[i];
        v.x = v.x * ga + be; v.y = v.y * ga + be;
        v.z = v.z * ga + be; v.w = v.w * ga + be;
        hp[i] = v;
    }
}

// ---------------- 1x1 conv projection: Out[b,m,n] = sum_c W[m,c]*H[b,c,n] + bias[m] (+resid) ----------------
// grid: (N/64, C/64, B); block 256; 64x64 tile, 4x4 per thread, K-step 16
__global__ void __launch_bounds__(256) proj_kernel(const float* __restrict__ W,
                                                   const float* __restrict__ bias,
                                                   const float* __restrict__ Hin,
                                                   const float* __restrict__ resid,
                                                   float* __restrict__ Out) {
    __shared__ float Ws[16][64];
    __shared__ float Hs[16][64];
    int b  = blockIdx.z;
    int m0 = blockIdx.y * 64;
    int n0 = blockIdx.x * 64;
    const float* Hb = Hin + (size_t)b * CCH * NPX;
    int tid = threadIdx.x;
    int tx = tid & 15, ty = tid >> 4;

    float acc[4][4] = {};
    for (int k0 = 0; k0 < CCH; k0 += 16) {
        {
            int row = tid >> 2;            // 0..63 (m)
            int kk  = (tid & 3) * 4;       // 0,4,8,12
            float4 w4 = *(const float4*)(W + (size_t)(m0 + row) * CCH + k0 + kk);
            Ws[kk + 0][row] = w4.x; Ws[kk + 1][row] = w4.y;
            Ws[kk + 2][row] = w4.z; Ws[kk + 3][row] = w4.w;
        }
        {
            int kk  = tid >> 4;            // 0..15
            int col = (tid & 15) * 4;
            *(float4*)&Hs[kk][col] = *(const float4*)(Hb + (size_t)(k0 + kk) * NPX + n0 + col);
        }
        __syncthreads();
        #pragma unroll
        for (int kk = 0; kk < 16; kk++) {
            float4 a  = *(const float4*)&Ws[kk][ty * 4];
            float4 bb = *(const float4*)&Hs[kk][tx * 4];
            acc[0][0] += a.x * bb.x; acc[0][1] += a.x * bb.y; acc[0][2] += a.x * bb.z; acc[0][3] += a.x * bb.w;
            acc[1][0] += a.y * bb.x; acc[1][1] += a.y * bb.y; acc[1][2] += a.y * bb.z; acc[1][3] += a.y * bb.w;
            acc[2][0] += a.z * bb.x; acc[2][1] += a.z * bb.y; acc[2][2] += a.z * bb.z; acc[2][3] += a.z * bb.w;
            acc[3][0] += a.w * bb.x; acc[3][1] += a.w * bb.y; acc[3][2] += a.w * bb.z; acc[3][3] += a.w * bb.w;
        }
        __syncthreads();
    }
    float* Ob = Out + (size_t)b * CCH * NPX;
    #pragma unroll
    for (int i = 0; i < 4; i++) {
        int m = m0 + ty * 4 + i;
        float bia = bias[m];
        size_t off = (size_t)b * CCH * NPX + (size_t)m * NPX + n0 + tx * 4;
        float4 v;
        v.x = acc[i][0] + bia; v.y = acc[i][1] + bia;
        v.z = acc[i][2] + bia; v.w = acc[i][3] + bia;
        if (resid) {
            float4 r = *(const float4*)(resid + off);
            v.x += r.x; v.y += r.y; v.z += r.z; v.w += r.w;
        }
        *(float4*)(Ob + (size_t)m * NPX + n0 + tx * 4) = v;
    }
}

// ---------------- scores: S[b,i,j] = scale * sum_c Q[b,c,i]*K[b,c,j] ----------------
// grid: (N/64 for j, N/64 for i, B)
__global__ void __launch_bounds__(256) scores_kernel(const float* __restrict__ Q,
                                                     const float* __restrict__ K,
                                                     float* __restrict__ S,
                                                     float scale) {
    __shared__ float Qs[16][64];
    __shared__ float Ks[16][64];
    int b  = blockIdx.z;
    int i0 = blockIdx.y * 64;
    int j0 = blockIdx.x * 64;
    const float* Qb = Q + (size_t)b * CCH * NPX;
    const float* Kb = K + (size_t)b * CCH * NPX;
    int tid = threadIdx.x;
    int tx = tid & 15, ty = tid >> 4;

    float acc[4][4] = {};
    for (int k0 = 0; k0 < CCH; k0 += 16) {
        int kk  = tid >> 4;
        int col = (tid & 15) * 4;
        *(float4*)&Qs[kk][col] = *(const float4*)(Qb + (size_t)(k0 + kk) * NPX + i0 + col);
        *(float4*)&Ks[kk][col] = *(const float4*)(Kb + (size_t)(k0 + kk) * NPX + j0 + col);
        __syncthreads();
        #pragma unroll
        for (int k2 = 0; k2 < 16; k2++) {
            float4 a  = *(const float4*)&Qs[k2][ty * 4];
            float4 bb = *(const float4*)&Ks[k2][tx * 4];
            acc[0][0] += a.x * bb.x; acc[0][1] += a.x * bb.y; acc[0][2] += a.x * bb.z; acc[0][3] += a.x * bb.w;
            acc[1][0] += a.y * bb.x; acc[1][1] += a.y * bb.y; acc[1][2] += a.y * bb.z; acc[1][3] += a.y * bb.w;
            acc[2][0] += a.z * bb.x; acc[2][1] += a.z * bb.y; acc[2][2] += a.z * bb.z; acc[2][3] += a.z * bb.w;
            acc[3][0] += a.w * bb.x; acc[3][1] += a.w * bb.y; acc[3][2] += a.w * bb.z; acc[3][3] += a.w * bb.w;
        }
        __syncthreads();
    }
    float* Sb = S + (size_t)b * NPX * NPX;
    #pragma unroll
    for (int i = 0; i < 4; i++) {
        int ii = i0 + ty * 4 + i;
        float4 v;
        v.x = acc[i][0] * scale; v.y = acc[i][1] * scale;
        v.z = acc[i][2] * scale; v.w = acc[i][3] * scale;
        *(float4*)(Sb + (size_t)ii * NPX + j0 + tx * 4) = v;
    }
}

// ---------------- softmax over rows of S (in place), register-resident ----------------
__global__ void __launch_bounds__(256) softmax_kernel(float* __restrict__ S) {
    size_t row = blockIdx.x;                 // 0 .. 2*4096-1
    float* p = S + row * NPX;
    int tid = threadIdx.x;
    float r[16];
    float m = -1e30f;
    #pragma unroll
    for (int i = 0; i < 16; i++) { r[i] = p[tid + i * 256]; m = fmaxf(m, r[i]); }

    __shared__ float red[8];
    #pragma unroll
    for (int o = 16; o > 0; o >>= 1) m = fmaxf(m, __shfl_xor_sync(0xffffffffu, m, o));
    if ((tid & 31) == 0) red[tid >> 5] = m;
    __syncthreads();
    float bm = red[0];
    #pragma unroll
    for (int w = 1; w < 8; w++) bm = fmaxf(bm, red[w]);
    __syncthreads();

    float s = 0.f;
    #pragma unroll
    for (int i = 0; i < 16; i++) { r[i] = __expf(r[i] - bm); s += r[i]; }
    #pragma unroll
    for (int o = 16; o > 0; o >>= 1) s += __shfl_xor_sync(0xffffffffu, s, o);
    if ((tid & 31) == 0) red[tid >> 5] = s;
    __syncthreads();
    float bs = 0.f;
    #pragma unroll
    for (int w = 0; w < 8; w++) bs += red[w];
    float inv = 1.0f / bs;
    #pragma unroll
    for (int i = 0; i < 16; i++) p[tid + i * 256] = r[i] * inv;
}

// ---------------- AV: O[b,c,i] = sum_j V[b,c,j] * A[b,i,j] ----------------
// grid: (N/64 for i, C/64 for c, B); reduction over j (4096)
__global__ void __launch_bounds__(256) av_kernel(const float* __restrict__ V,
                                                 const float* __restrict__ A,
                                                 float* __restrict__ O) {
    __shared__ float Vs[16][64];
    __shared__ float As[16][64];
    int b  = blockIdx.z;
    int i0 = blockIdx.x * 64;
    int c0 = blockIdx.y * 64;
    const float* Vb = V + (size_t)b * CCH * NPX;
    const float* Ab = A + (size_t)b * NPX * NPX;
    int tid = threadIdx.x;
    int tx = tid & 15, ty = tid >> 4;

    float acc[4][4] = {};
    for (int j0 = 0; j0 < NPX; j0 += 16) {
        {
            int row = tid >> 2;            // 0..63
            int jj  = (tid & 3) * 4;
            float4 v4 = *(const float4*)(Vb + (size_t)(c0 + row) * NPX + j0 + jj);
            Vs[jj + 0][row] = v4.x; Vs[jj + 1][row] = v4.y;
            Vs[jj + 2][row] = v4.z; Vs[jj + 3][row] = v4.w;
            float4 a4 = *(const float4*)(Ab + (size_t)(i0 + row) * NPX + j0 + jj);
            As[jj + 0][row] = a4.x; As[jj + 1][row] = a4.y;
            As[jj + 2][row] = a4.z; As[jj + 3][row] = a4.w;
        }
        __syncthreads();
        #pragma unroll
        for (int kk = 0; kk < 16; kk++) {
            float4 a  = *(const float4*)&Vs[kk][ty * 4];   // 4 channels
            float4 bb = *(const float4*)&As[kk][tx * 4];   // 4 pixels i
            acc[0][0] += a.x * bb.x; acc[0][1] += a.x * bb.y; acc[0][2] += a.x * bb.z; acc[0][3] += a.x * bb.w;
            acc[1][0] += a.y * bb.x; acc[1][1] += a.y * bb.y; acc[1][2] += a.y * bb.z; acc[1][3] += a.y * bb.w;
            acc[2][0] += a.z * bb.x; acc[2][1] += a.z * bb.y; acc[2][2] += a.z * bb.z; acc[2][3] += a.z * bb.w;
            acc[3][0] += a.w * bb.x; acc[3][1] += a.w * bb.y; acc[3][2] += a.w * bb.z; acc[3][3] += a.w * bb.w;
        }
        __syncthreads();
    }
    float* Ob = O + (size_t)b * CCH * NPX;
    #pragma unroll
    for (int ci = 0; ci < 4; ci++) {
        int c = c0 + ty * 4 + ci;
        float4 v;
        v.x = acc[ci][0]; v.y = acc[ci][1]; v.z = acc[ci][2]; v.w = acc[ci][3];
        *(float4*)(Ob + (size_t)c * NPX + i0 + tx * 4) = v;
    }
}

// ---------------- launch ----------------
extern "C" void kernel_launch(void* const* d_in, const int* in_sizes, int n_in,
                              void* d_out, int out_size) {
    const float* x     = (const float*)d_in[0];
    const float* gamma = (const float*)d_in[1];
    const float* beta  = (const float*)d_in[2];
    const float* wq    = (const float*)d_in[3];
    const float* bq    = (const float*)d_in[4];
    const float* wk    = (const float*)d_in[5];
    const float* bk    = (const float*)d_in[6];
    const float* wv    = (const float*)d_in[7];
    const float* bv    = (const float*)d_in[8];
    const float* wp    = (const float*)d_in[9];
    const float* bp    = (const float*)d_in[10];
    float* out = (float*)d_out;

    float *ph, *pq, *pk, *pv, *po, *ps;
    cudaGetSymbolAddress((void**)&ph, g_h);
    cudaGetSymbolAddress((void**)&pq, g_q);
    cudaGetSymbolAddress((void**)&pk, g_k);
    cudaGetSymbolAddress((void**)&pv, g_v);
    cudaGetSymbolAddress((void**)&po, g_o);
    cudaGetSymbolAddress((void**)&ps, g_s);

    // 1. GroupNorm
    gn_kernel<<<64, 256>>>(x, gamma, beta, ph);

    // 2. Q, K, V projections
    dim3 gproj(NPX / 64, CCH / 64, 2);
    proj_kernel<<<gproj, 256>>>(wq, bq, ph, nullptr, pq);
    proj_kernel<<<gproj, 256>>>(wk, bk, ph, nullptr, pk);
    proj_kernel<<<gproj, 256>>>(wv, bv, ph, nullptr, pv);

    // 3. scores = scale * Q^T K
    const float scale = 1.0f / sqrtf((float)CCH);
    dim3 gsc(NPX / 64, NPX / 64, 2);
    scores_kernel<<<gsc, 256>>>(pq, pk, ps, scale);

    // 4. softmax rows
    softmax_kernel<<<2 * NPX, 256>>>(ps);

    // 5. O = V * Attn^T
    dim3 gav(NPX / 64, CCH / 64, 2);
    av_kernel<<<gav, 256>>>(pv, ps, po);

    // 6. out = x + Wp * O + bp   (residual)
    proj_kernel<<<gproj, 256>>>(wp, bp, po, x, out);
}

// round 3
// speedup vs baseline: 2.4144x; 2.4144x over previous
#include <cuda_runtime.h>
#include <cuda_bf16.h>
#include <math.h>
#include <stdint.h>

#define CCH 512
#define NPX 4096
typedef __nv_bfloat16 bf16;

static const size_t NH = (size_t)NPX * CCH;
static const size_t NN = (size_t)NPX * NPX;
#define WS ((size_t)CCH * CCH)

// ---------------- static scratch ----------------
__device__ bf16 g_ht_hi[(size_t)2 * NPX * CCH];   // GN output [B][N][C]
__device__ bf16 g_ht_lo[(size_t)2 * NPX * CCH];
__device__ bf16 g_w_hi[(size_t)4 * CCH * CCH];
__device__ bf16 g_w_lo[(size_t)4 * CCH * CCH];
__device__ bf16 g_q_hi[(size_t)2 * NPX * CCH];
__device__ bf16 g_q_lo[(size_t)2 * NPX * CCH];
__device__ bf16 g_k_hi[(size_t)2 * NPX * CCH];
__device__ bf16 g_k_lo[(size_t)2 * NPX * CCH];
__device__ bf16 g_v_hi[(size_t)2 * CCH * NPX];    // [B][C][N]
__device__ bf16 g_v_lo[(size_t)2 * CCH * NPX];
__device__ bf16 g_o_hi[(size_t)2 * NPX * CCH];    // [B][N][C]
__device__ bf16 g_o_lo[(size_t)2 * NPX * CCH];
__device__ float g_s[(size_t)2 * NPX * NPX];
__device__ bf16 g_a_hi[(size_t)2 * NPX * NPX];
__device__ bf16 g_a_lo[(size_t)2 * NPX * NPX];

// ---------------- helpers ----------------
__device__ __forceinline__ uint32_t smem_u32(const void* p) {
    uint32_t a;
    asm("{ .reg .u64 t; cvta.to.shared.u64 t, %1; cvt.u32.u64 %0, t; }" : "=r"(a) : "l"(p));
    return a;
}
__device__ __forceinline__ void splitf(float v, bf16& h, bf16& l) {
    h = __float2bfloat16(v);
    l = __float2bfloat16(v - __bfloat162float(h));
}
__device__ __forceinline__ uint32_t pack2(bf16 a, bf16 b) {
    __nv_bfloat162 t; t.x = a; t.y = b;
    return *reinterpret_cast<uint32_t*>(&t);
}
__device__ __forceinline__ void cp16(uint32_t s, const void* g) {
    asm volatile("cp.async.cg.shared.global [%0], [%1], 16;" :: "r"(s), "l"(g));
}
__device__ __forceinline__ void ldsm4(uint32_t* r, uint32_t addr) {
    asm volatile("ldmatrix.sync.aligned.m8n8.x4.shared.b16 {%0,%1,%2,%3}, [%4];"
        : "=r"(r[0]), "=r"(r[1]), "=r"(r[2]), "=r"(r[3]) : "r"(addr));
}
__device__ __forceinline__ void mma16816(float* d, const uint32_t* a, uint32_t b0, uint32_t b1) {
    asm volatile("mma.sync.aligned.m16n8k16.row.col.f32.bf16.bf16.f32 "
        "{%0,%1,%2,%3}, {%4,%5,%6,%7}, {%8,%9}, {%0,%1,%2,%3};"
        : "+f"(d[0]), "+f"(d[1]), "+f"(d[2]), "+f"(d[3])
        : "r"(a[0]), "r"(a[1]), "r"(a[2]), "r"(a[3]), "r"(b0), "r"(b1));
}

// ---------------- weight split ----------------
__global__ void __launch_bounds__(256) wconv_kernel(const float* __restrict__ w,
                                                    bf16* __restrict__ hi, bf16* __restrict__ lo) {
    int i = blockIdx.x * 256 + threadIdx.x;
    float v = w[i];
    bf16 h, l; splitf(v, h, l);
    hi[i] = h; lo[i] = l;
}

// ---------------- GroupNorm + transpose + split: x[B,C,N] -> hT[B,N,C] hi/lo ----------------
__global__ void __launch_bounds__(256) gn_kernel(const float* __restrict__ x,
                                                 const float* __restrict__ gamma,
                                                 const float* __restrict__ beta,
                                                 bf16* __restrict__ hthi, bf16* __restrict__ htlo) {
    int b = blockIdx.x >> 5;
    int g = blockIdx.x & 31;
    const size_t base = ((size_t)b * CCH + (size_t)g * 16) * NPX;
    const float4* xp = (const float4*)(x + base);
    const int TOT4 = 16 * NPX / 4;
    int tid = threadIdx.x;

    float s = 0.f, ss = 0.f;
    for (int i = tid; i < TOT4; i += 256) {
        float4 v = xp[i];
        s  += v.x + v.y + v.z + v.w;
        ss += v.x * v.x + v.y * v.y + v.z * v.z + v.w * v.w;
    }
    __shared__ float rs[8], rss[8];
    #pragma unroll
    for (int o = 16; o > 0; o >>= 1) {
        s  += __shfl_xor_sync(0xffffffffu, s, o);
        ss += __shfl_xor_sync(0xffffffffu, ss, o);
    }
    if ((tid & 31) == 0) { rs[tid >> 5] = s; rss[tid >> 5] = ss; }
    __syncthreads();
    float S = 0.f, SS = 0.f;
    #pragma unroll
    for (int w = 0; w < 8; w++) { S += rs[w]; SS += rss[w]; }
    const float inv_cnt = 1.0f / (float)(16 * NPX);
    float mean = S * inv_cnt;
    float var  = SS * inv_cnt - mean * mean;
    float rstd = rsqrtf(var + 1e-6f);

    __shared__ float sga[16], sbe[16];
    if (tid < 16) {
        int c = g * 16 + tid;
        float ga = gamma[c] * rstd;
        sga[tid] = ga;
        sbe[tid] = beta[c] - mean * ga;
    }
    __shared__ float xs[16][256];
    __syncthreads();

    for (int p0 = 0; p0 < NPX; p0 += 256) {
        #pragma unroll
        for (int c = 0; c < 16; c++) xs[c][tid] = x[base + (size_t)c * NPX + p0 + tid];
        __syncthreads();
        uint32_t hw[8], lw[8];
        #pragma unroll
        for (int c2 = 0; c2 < 8; c2++) {
            float v0 = xs[2 * c2][tid]     * sga[2 * c2]     + sbe[2 * c2];
            float v1 = xs[2 * c2 + 1][tid] * sga[2 * c2 + 1] + sbe[2 * c2 + 1];
            bf16 h0, l0, h1, l1;
            splitf(v0, h0, l0); splitf(v1, h1, l1);
            hw[c2] = pack2(h0, h1); lw[c2] = pack2(l0, l1);
        }
        size_t o = ((size_t)b * NPX + p0 + tid) * CCH + g * 16;
        ((uint4*)(hthi + o))[0] = make_uint4(hw[0], hw[1], hw[2], hw[3]);
        ((uint4*)(hthi + o))[1] = make_uint4(hw[4], hw[5], hw[6], hw[7]);
        ((uint4*)(htlo + o))[0] = make_uint4(lw[0], lw[1], lw[2], lw[3]);
        ((uint4*)(htlo + o))[1] = make_uint4(lw[4], lw[5], lw[6], lw[7]);
        __syncthreads();
    }
}

// ---------------- softmax fp32 -> bf16 hi/lo ----------------
__global__ void __launch_bounds__(256) softmax_kernel(const float* __restrict__ S,
                                                      bf16* __restrict__ ahi, bf16* __restrict__ alo) {
    size_t row = blockIdx.x;
    const float* p = S + row * NPX;
    int tid = threadIdx.x;
    float r[16];
    float m = -1e30f;
    #pragma unroll
    for (int i = 0; i < 16; i++) { r[i] = p[tid + i * 256]; m = fmaxf(m, r[i]); }
    __shared__ float red[8];
    #pragma unroll
    for (int o = 16; o > 0; o >>= 1) m = fmaxf(m, __shfl_xor_sync(0xffffffffu, m, o));
    if ((tid & 31) == 0) red[tid >> 5] = m;
    __syncthreads();
    float bm = red[0];
    #pragma unroll
    for (int w = 1; w < 8; w++) bm = fmaxf(bm, red[w]);
    __syncthreads();
    float s = 0.f;
    #pragma unroll
    for (int i = 0; i < 16; i++) { r[i] = __expf(r[i] - bm); s += r[i]; }
    #pragma unroll
    for (int o = 16; o > 0; o >>= 1) s += __shfl_xor_sync(0xffffffffu, s, o);
    if ((tid & 31) == 0) red[tid >> 5] = s;
    __syncthreads();
    float bs = 0.f;
    #pragma unroll
    for (int w = 0; w < 8; w++) bs += red[w];
    float inv = 1.0f / bs;
    #pragma unroll
    for (int i = 0; i < 16; i++) {
        float val = r[i] * inv;
        bf16 h, l; splitf(val, h, l);
        size_t idx = row * NPX + tid + i * 256;
        ahi[idx] = h; alo[idx] = l;
    }
}

// ---------------- bf16x3 HMMA GEMM ----------------
// D[m][n] = scale*sum_k A[m][k]*B[n][k] (+biasRow[m] +biasCol[n] +resid) via
// 3 bf16 passes (hi*hi + hi*lo + lo*hi) with fp32 accumulators.
// CTA tile 128x128, warp tile 64x32, BK=32, double-buffered cp.async.
#define TILE_B 10240          // 128 rows * 40 elems * 2B
__global__ void __launch_bounds__(256, 2) gemm_hmma(
    const bf16* __restrict__ Ahi, const bf16* __restrict__ Alo, size_t strideA,
    const bf16* __restrict__ Bhi, const bf16* __restrict__ Blo, size_t strideB,
    int K,
    float* __restrict__ outF32, bf16* __restrict__ outHi, bf16* __restrict__ outLo,
    int ldD, size_t strideD,
    float scale,
    const float* __restrict__ biasRow, const float* __restrict__ biasCol,
    const float* __restrict__ resid)
{
    extern __shared__ char smemraw[];
    int tid = threadIdx.x, wid = tid >> 5, lane = tid & 31;
    int m0 = blockIdx.y * 128, n0 = blockIdx.x * 128, bz = blockIdx.z;
    Ahi += (size_t)bz * strideA; Alo += (size_t)bz * strideA;
    Bhi += (size_t)bz * strideB; Blo += (size_t)bz * strideB;

    uint32_t base = smem_u32(smemraw);
    int wm = wid >> 2, wn = wid & 3;

    const int kc_per = K >> 5;       // chunks of 32
    const int nch = 3 * kc_per;

    float acc[4][4][4];
    #pragma unroll
    for (int a = 0; a < 4; a++)
        #pragma unroll
        for (int b = 0; b < 4; b++)
            #pragma unroll
            for (int c = 0; c < 4; c++) acc[a][b][c] = 0.f;

    auto load_chunk = [&](int i) {
        int b = i & 1;
        int seg = i / kc_per;
        int kc = i - seg * kc_per;
        const bf16* Ap = (seg < 2) ? Ahi : Alo;
        const bf16* Bp = (seg == 1) ? Blo : Bhi;
        size_t kb = (size_t)kc * 32;
        uint32_t sa = base + (b ? TILE_B : 0);
        uint32_t sb = base + 2 * TILE_B + (b ? TILE_B : 0);
        #pragma unroll
        for (int r = 0; r < 2; r++) {
            int u = tid + r * 256;
            int row = u >> 2, cs = u & 3;
            uint32_t off = (uint32_t)(row * 80 + cs * 16);
            cp16(sa + off, Ap + (size_t)(m0 + row) * K + kb + cs * 8);
            cp16(sb + off, Bp + (size_t)(n0 + row) * K + kb + cs * 8);
        }
    };

    load_chunk(0);
    asm volatile("cp.async.commit_group;" ::: "memory");

    for (int i = 0; i < nch; i++) {
        int b = i & 1;
        if (i + 1 < nch) {
            load_chunk(i + 1);
            asm volatile("cp.async.commit_group;" ::: "memory");
            asm volatile("cp.async.wait_group 1;" ::: "memory");
        } else {
            asm volatile("cp.async.wait_group 0;" ::: "memory");
        }
        __syncthreads();   // chunk i visible to all warps

        uint32_t sa = base + (b ? TILE_B : 0);
        uint32_t sb = base + 2 * TILE_B + (b ? TILE_B : 0);

        #pragma unroll
        for (int kk = 0; kk < 2; kk++) {
            uint32_t afr[4][4], bfr[2][4];
            #pragma unroll
            for (int mi = 0; mi < 4; mi++) {
                int row = wm * 64 + mi * 16 + (lane & 15);
                int kc  = kk * 16 + (lane >> 4) * 8;
                ldsm4(afr[mi], sa + (uint32_t)(row * 80 + kc * 2));
            }
            #pragma unroll
            for (int nb = 0; nb < 2; nb++) {
                int row = wn * 32 + nb * 16 + ((lane >> 4) << 3) + (lane & 7);
                int kc  = kk * 16 + (((lane >> 3) & 1) << 3);
                ldsm4(bfr[nb], sb + (uint32_t)(row * 80 + kc * 2));
            }
            #pragma unroll
            for (int mi = 0; mi < 4; mi++)
                #pragma unroll
                for (int ni = 0; ni < 4; ni++)
                    mma16816(acc[mi][ni], afr[mi],
                             bfr[ni >> 1][(ni & 1) * 2], bfr[ni >> 1][(ni & 1) * 2 + 1]);
        }
        __syncthreads();   // done reading buffer b before iter i+1 overwrites b^1's sibling
    }

    // ---------------- epilogue ----------------
    int r4 = lane >> 2;          // 0..7
    int c2 = lane & 3;           // 0..3
    float* of = outF32 ? outF32 + (size_t)bz * strideD : nullptr;
    bf16* ohp = outHi ? outHi + (size_t)bz * strideD : nullptr;
    bf16* olp = outLo ? outLo + (size_t)bz * strideD : nullptr;
    const float* rp = resid ? resid + (size_t)bz * strideD : nullptr;

    #pragma unroll
    for (int mi = 0; mi < 4; mi++) {
        #pragma unroll
        for (int half = 0; half < 2; half++) {
            int m = m0 + wm * 64 + mi * 16 + half * 8 + r4;
            float brow = biasRow ? biasRow[m] : 0.f;
            #pragma unroll
            for (int ni = 0; ni < 4; ni++) {
                int n = n0 + wn * 32 + ni * 8 + c2 * 2;
                float v0 = acc[mi][ni][half * 2 + 0] * scale + brow;
                float v1 = acc[mi][ni][half * 2 + 1] * scale + brow;
                if (biasCol) { v0 += biasCol[n]; v1 += biasCol[n + 1]; }
                size_t off = (size_t)m * ldD + n;
                if (rp) {
                    float2 q = *(const float2*)(rp + off);
                    v0 += q.x; v1 += q.y;
                }
                if (of) *(float2*)(of + off) = make_float2(v0, v1);
                if (ohp) {
                    bf16 h0, l0, h1, l1;
                    splitf(v0, h0, l0); splitf(v1, h1, l1);
                    *(uint32_t*)(ohp + off) = pack2(h0, h1);
                    *(uint32_t*)(olp + off) = pack2(l0, l1);
                }
            }
        }
    }
}

// ---------------- launch ----------------
extern "C" void kernel_launch(void* const* d_in, const int* in_sizes, int n_in,
                              void* d_out, int out_size) {
    const float* x     = (const float*)d_in[0];
    const float* gamma = (const float*)d_in[1];
    const float* beta  = (const float*)d_in[2];
    const float* wq    = (const float*)d_in[3];
    const float* bq    = (const float*)d_in[4];
    const float* wk    = (const float*)d_in[5];
    const float* bk    = (const float*)d_in[6];
    const float* wv    = (const float*)d_in[7];
    const float* bv    = (const float*)d_in[8];
    const float* wp    = (const float*)d_in[9];
    const float* bp    = (const float*)d_in[10];
    float* out = (float*)d_out;

    bf16 *hthi, *htlo, *whi, *wlo, *qhi, *qlo, *khi, *klo, *vhi, *vlo, *ohi, *olo, *ahi, *alo;
    float* ps;
    cudaGetSymbolAddress((void**)&hthi, g_ht_hi); cudaGetSymbolAddress((void**)&htlo, g_ht_lo);
    cudaGetSymbolAddress((void**)&whi, g_w_hi);   cudaGetSymbolAddress((void**)&wlo, g_w_lo);
    cudaGetSymbolAddress((void**)&qhi, g_q_hi);   cudaGetSymbolAddress((void**)&qlo, g_q_lo);
    cudaGetSymbolAddress((void**)&khi, g_k_hi);   cudaGetSymbolAddress((void**)&klo, g_k_lo);
    cudaGetSymbolAddress((void**)&vhi, g_v_hi);   cudaGetSymbolAddress((void**)&vlo, g_v_lo);
    cudaGetSymbolAddress((void**)&ohi, g_o_hi);   cudaGetSymbolAddress((void**)&olo, g_o_lo);
    cudaGetSymbolAddress((void**)&ahi, g_a_hi);   cudaGetSymbolAddress((void**)&alo, g_a_lo);
    cudaGetSymbolAddress((void**)&ps, g_s);

    const int SMEM_DYN = 4 * TILE_B;    // 40 KB
    cudaFuncSetAttribute(gemm_hmma, cudaFuncAttributeMaxDynamicSharedMemorySize, SMEM_DYN);

    wconv_kernel<<<CCH * CCH / 256, 256>>>(wq, whi + 0 * WS, wlo + 0 * WS);
    wconv_kernel<<<CCH * CCH / 256, 256>>>(wk, whi + 1 * WS, wlo + 1 * WS);
    wconv_kernel<<<CCH * CCH / 256, 256>>>(wv, whi + 2 * WS, wlo + 2 * WS);
    wconv_kernel<<<CCH * CCH / 256, 256>>>(wp, whi + 3 * WS, wlo + 3 * WS);

    gn_kernel<<<64, 256>>>(x, gamma, beta, hthi, htlo);

    // Q = hT @ Wq^T : [4096,512], biasCol=bq
    gemm_hmma<<<dim3(CCH / 128, NPX / 128, 2), 256, SMEM_DYN>>>(
        hthi, htlo, NH, whi + 0 * WS, wlo + 0 * WS, 0, CCH,
        nullptr, qhi, qlo, CCH, NH, 1.0f, nullptr, bq, nullptr);
    // K
    gemm_hmma<<<dim3(CCH / 128, NPX / 128, 2), 256, SMEM_DYN>>>(
        hthi, htlo, NH, whi + 1 * WS, wlo + 1 * WS, 0, CCH,
        nullptr, khi, klo, CCH, NH, 1.0f, nullptr, bk, nullptr);
    // V = Wv @ hT^T : [512,4096], biasRow=bv
    gemm_hmma<<<dim3(NPX / 128, CCH / 128, 2), 256, SMEM_DYN>>>(
        whi + 2 * WS, wlo + 2 * WS, 0, hthi, htlo, NH, CCH,
        nullptr, vhi, vlo, NPX, NH, 1.0f, bv, nullptr, nullptr);

    // scores = scale * Q @ K^T : fp32 [4096,4096]
    const float scale = 1.0f / sqrtf((float)CCH);
    gemm_hmma<<<dim3(NPX / 128, NPX / 128, 2), 256, SMEM_DYN>>>(
        qhi, qlo, NH, khi, klo, NH, CCH,
        ps, nullptr, nullptr, NPX, NN, scale, nullptr, nullptr, nullptr);

    softmax_kernel<<<2 * NPX, 256>>>(ps, ahi, alo);

    // O = attn @ V^T : [4096,512]
    gemm_hmma<<<dim3(CCH / 128, NPX / 128, 2), 256, SMEM_DYN>>>(
        ahi, alo, NN, vhi, vlo, NH, NPX,
        nullptr, ohi, olo, CCH, NH, 1.0f, nullptr, nullptr, nullptr);

    // out = x + Wp @ O^T + bp : fp32 [512,4096]
    gemm_hmma<<<dim3(NPX / 128, CCH / 128, 2), 256, SMEM_DYN>>>(
        whi + 3 * WS, wlo + 3 * WS, 0, ohi, olo, NH, CCH,
        out, nullptr, nullptr, NPX, (size_t)CCH * NPX, 1.0f, bp, nullptr, x);
}

// round 4
// speedup vs baseline: 2.5288x; 1.0474x over previous
#include <cuda_runtime.h>
#include <cuda_bf16.h>
#include <math.h>
#include <stdint.h>

#define CCH 512
#define NPX 4096
typedef __nv_bfloat16 bf16;

static const size_t NH  = (size_t)NPX * CCH;
static const size_t NN  = (size_t)NPX * NPX;
static const size_t NQK = (size_t)NPX * 1024;
#define WS ((size_t)CCH * CCH)

// ---------------- static scratch ----------------
__device__ bf16 g_ht_hi[(size_t)2 * NPX * CCH];   // GN output [B][N][C]
__device__ bf16 g_ht_lo[(size_t)2 * NPX * CCH];
__device__ bf16 g_w_hi[(size_t)4 * CCH * CCH];    // wq,wk,wv,wp (contig: [wq;wk] = [1024,512])
__device__ bf16 g_w_lo[(size_t)4 * CCH * CCH];
__device__ bf16 g_qk_hi[(size_t)2 * NPX * 1024];  // [B][N][1024]: Q cols 0-511, K cols 512-1023
__device__ bf16 g_qk_lo[(size_t)2 * NPX * 1024];
__device__ bf16 g_v_hi[(size_t)2 * CCH * NPX];    // [B][C][N]
__device__ bf16 g_v_lo[(size_t)2 * CCH * NPX];
__device__ bf16 g_o_hi[(size_t)2 * NPX * CCH];    // [B][N][C]
__device__ bf16 g_o_lo[(size_t)2 * NPX * CCH];
__device__ float g_s[(size_t)2 * NPX * NPX];
__device__ bf16 g_a_hi[(size_t)2 * NPX * NPX];
__device__ bf16 g_a_lo[(size_t)2 * NPX * NPX];

// ---------------- helpers ----------------
__device__ __forceinline__ uint32_t smem_u32(const void* p) {
    uint32_t a;
    asm("{ .reg .u64 t; cvta.to.shared.u64 t, %1; cvt.u32.u64 %0, t; }" : "=r"(a) : "l"(p));
    return a;
}
__device__ __forceinline__ void splitf(float v, bf16& h, bf16& l) {
    h = __float2bfloat16(v);
    l = __float2bfloat16(v - __bfloat162float(h));
}
__device__ __forceinline__ uint32_t pack2(bf16 a, bf16 b) {
    __nv_bfloat162 t; t.x = a; t.y = b;
    return *reinterpret_cast<uint32_t*>(&t);
}
__device__ __forceinline__ void cp16(uint32_t s, const void* g) {
    asm volatile("cp.async.cg.shared.global [%0], [%1], 16;" :: "r"(s), "l"(g));
}
__device__ __forceinline__ void ldsm4(uint32_t* r, uint32_t addr) {
    asm volatile("ldmatrix.sync.aligned.m8n8.x4.shared.b16 {%0,%1,%2,%3}, [%4];"
        : "=r"(r[0]), "=r"(r[1]), "=r"(r[2]), "=r"(r[3]) : "r"(addr));
}
__device__ __forceinline__ void mma16816(float* d, const uint32_t* a, uint32_t b0, uint32_t b1) {
    asm volatile("mma.sync.aligned.m16n8k16.row.col.f32.bf16.bf16.f32 "
        "{%0,%1,%2,%3}, {%4,%5,%6,%7}, {%8,%9}, {%0,%1,%2,%3};"
        : "+f"(d[0]), "+f"(d[1]), "+f"(d[2]), "+f"(d[3])
        : "r"(a[0]), "r"(a[1]), "r"(a[2]), "r"(a[3]), "r"(b0), "r"(b1));
}

// ---------------- weight split (all 4 matrices in one launch) ----------------
__global__ void __launch_bounds__(256) wconv_kernel(const float* __restrict__ w0,
                                                    const float* __restrict__ w1,
                                                    const float* __restrict__ w2,
                                                    const float* __restrict__ w3,
                                                    bf16* __restrict__ hi, bf16* __restrict__ lo) {
    size_t i = (size_t)blockIdx.x * 256 + threadIdx.x;
    size_t which = i / WS, r = i - which * WS;
    const float* w = (which == 0) ? w0 : (which == 1) ? w1 : (which == 2) ? w2 : w3;
    float v = w[r];
    bf16 h, l; splitf(v, h, l);
    hi[i] = h; lo[i] = l;
}

// ---------------- GroupNorm + transpose + split ----------------
__global__ void __launch_bounds__(256) gn_kernel(const float* __restrict__ x,
                                                 const float* __restrict__ gamma,
                                                 const float* __restrict__ beta,
                                                 bf16* __restrict__ hthi, bf16* __restrict__ htlo) {
    int b = blockIdx.x >> 5;
    int g = blockIdx.x & 31;
    const size_t base = ((size_t)b * CCH + (size_t)g * 16) * NPX;
    const float4* xp = (const float4*)(x + base);
    const int TOT4 = 16 * NPX / 4;
    int tid = threadIdx.x;

    float s = 0.f, ss = 0.f;
    for (int i = tid; i < TOT4; i += 256) {
        float4 v = xp[i];
        s  += v.x + v.y + v.z + v.w;
        ss += v.x * v.x + v.y * v.y + v.z * v.z + v.w * v.w;
    }
    __shared__ float rs[8], rss[8];
    #pragma unroll
    for (int o = 16; o > 0; o >>= 1) {
        s  += __shfl_xor_sync(0xffffffffu, s, o);
        ss += __shfl_xor_sync(0xffffffffu, ss, o);
    }
    if ((tid & 31) == 0) { rs[tid >> 5] = s; rss[tid >> 5] = ss; }
    __syncthreads();
    float S = 0.f, SS = 0.f;
    #pragma unroll
    for (int w = 0; w < 8; w++) { S += rs[w]; SS += rss[w]; }
    const float inv_cnt = 1.0f / (float)(16 * NPX);
    float mean = S * inv_cnt;
    float var  = SS * inv_cnt - mean * mean;
    float rstd = rsqrtf(var + 1e-6f);

    __shared__ float sga[16], sbe[16];
    if (tid < 16) {
        int c = g * 16 + tid;
        float ga = gamma[c] * rstd;
        sga[tid] = ga;
        sbe[tid] = beta[c] - mean * ga;
    }
    __shared__ float xs[16][256];
    __syncthreads();

    for (int p0 = 0; p0 < NPX; p0 += 256) {
        #pragma unroll
        for (int c = 0; c < 16; c++) xs[c][tid] = x[base + (size_t)c * NPX + p0 + tid];
        __syncthreads();
        uint32_t hw[8], lw[8];
        #pragma unroll
        for (int c2 = 0; c2 < 8; c2++) {
            float v0 = xs[2 * c2][tid]     * sga[2 * c2]     + sbe[2 * c2];
            float v1 = xs[2 * c2 + 1][tid] * sga[2 * c2 + 1] + sbe[2 * c2 + 1];
            bf16 h0, l0, h1, l1;
            splitf(v0, h0, l0); splitf(v1, h1, l1);
            hw[c2] = pack2(h0, h1); lw[c2] = pack2(l0, l1);
        }
        size_t o = ((size_t)b * NPX + p0 + tid) * CCH + g * 16;
        ((uint4*)(hthi + o))[0] = make_uint4(hw[0], hw[1], hw[2], hw[3]);
        ((uint4*)(hthi + o))[1] = make_uint4(hw[4], hw[5], hw[6], hw[7]);
        ((uint4*)(htlo + o))[0] = make_uint4(lw[0], lw[1], lw[2], lw[3]);
        ((uint4*)(htlo + o))[1] = make_uint4(lw[4], lw[5], lw[6], lw[7]);
        __syncthreads();
    }
}

// ---------------- softmax fp32 -> bf16 hi/lo (packed stores) ----------------
__global__ void __launch_bounds__(256) softmax_kernel(const float* __restrict__ S,
                                                      bf16* __restrict__ ahi, bf16* __restrict__ alo) {
    size_t row = blockIdx.x;
    const float* p = S + row * NPX;
    int tid = threadIdx.x;
    float2 r[8];
    float m = -1e30f;
    #pragma unroll
    for (int i = 0; i < 8; i++) {
        r[i] = *(const float2*)(p + tid * 2 + i * 512);
        m = fmaxf(m, fmaxf(r[i].x, r[i].y));
    }
    __shared__ float red[8];
    #pragma unroll
    for (int o = 16; o > 0; o >>= 1) m = fmaxf(m, __shfl_xor_sync(0xffffffffu, m, o));
    if ((tid & 31) == 0) red[tid >> 5] = m;
    __syncthreads();
    float bm = red[0];
    #pragma unroll
    for (int w = 1; w < 8; w++) bm = fmaxf(bm, red[w]);
    __syncthreads();
    float s = 0.f;
    #pragma unroll
    for (int i = 0; i < 8; i++) {
        r[i].x = __expf(r[i].x - bm); r[i].y = __expf(r[i].y - bm);
        s += r[i].x + r[i].y;
    }
    #pragma unroll
    for (int o = 16; o > 0; o >>= 1) s += __shfl_xor_sync(0xffffffffu, s, o);
    if ((tid & 31) == 0) red[tid >> 5] = s;
    __syncthreads();
    float bs = 0.f;
    #pragma unroll
    for (int w = 0; w < 8; w++) bs += red[w];
    float inv = 1.0f / bs;
    #pragma unroll
    for (int i = 0; i < 8; i++) {
        float v0 = r[i].x * inv, v1 = r[i].y * inv;
        bf16 h0, l0, h1, l1;
        splitf(v0, h0, l0); splitf(v1, h1, l1);
        size_t idx = row * NPX + tid * 2 + i * 512;
        *(uint32_t*)(ahi + idx) = pack2(h0, h1);
        *(uint32_t*)(alo + idx) = pack2(l0, l1);
    }
}

// ---------------- bf16x3 HMMA GEMM, BK=64, 3-stage, 1 sync/chunk ----------------
// D[m][n] = scale*sum_k A[m][k]*B[n][k] (+biasRow[m] +biasCol[n] +resid)
#define PADE 72                  // padded row stride in elems (144 B)
#define STG_A (128 * PADE * 2)   // 18432 B
#define STG  (2 * STG_A)         // A+B per stage: 36864 B
__global__ void __launch_bounds__(256) gemm_hmma(
    const bf16* __restrict__ Ahi, const bf16* __restrict__ Alo, int ldA, size_t strideA,
    const bf16* __restrict__ Bhi, const bf16* __restrict__ Blo, int ldB, size_t strideB,
    int K,
    float* __restrict__ outF32, bf16* __restrict__ outHi, bf16* __restrict__ outLo,
    int ldD, size_t strideD,
    float scale,
    const float* __restrict__ biasRow,
    const float* __restrict__ biasCol, const float* __restrict__ biasCol2,
    const float* __restrict__ resid)
{
    extern __shared__ char smemraw[];
    int tid = threadIdx.x, wid = tid >> 5, lane = tid & 31;
    int m0 = blockIdx.y * 128, n0 = blockIdx.x * 128, bz = blockIdx.z;
    Ahi += (size_t)bz * strideA; Alo += (size_t)bz * strideA;
    Bhi += (size_t)bz * strideB; Blo += (size_t)bz * strideB;

    uint32_t base = smem_u32(smemraw);
    int wm = wid >> 2, wn = wid & 3;

    const int kc_per = K >> 6;       // chunks of 64
    const int nch = 3 * kc_per;

    float acc[4][4][4];
    #pragma unroll
    for (int a = 0; a < 4; a++)
        #pragma unroll
        for (int b = 0; b < 4; b++)
            #pragma unroll
            for (int c = 0; c < 4; c++) acc[a][b][c] = 0.f;

    // per-thread load slots: 4 A + 4 B per stage
    int lrow = tid >> 1;                     // shared by pairs? no: u mapping below
    auto load_chunk = [&](int i) {
        int st = i % 3;
        int seg = i / kc_per;
        int kc = i - seg * kc_per;
        const bf16* Ap = (seg < 2) ? Ahi : Alo;
        const bf16* Bp = (seg == 1) ? Blo : Bhi;
        size_t kb = (size_t)kc * 64;
        uint32_t sa = base + st * STG;
        uint32_t sb = sa + STG_A;
        #pragma unroll
        for (int r = 0; r < 4; r++) {
            int u = tid + r * 256;           // 0..1023
            int row = u >> 3, cs = u & 7;
            uint32_t off = (uint32_t)(row * 144 + cs * 16);
            cp16(sa + off, Ap + (size_t)(m0 + row) * ldA + kb + cs * 8);
            cp16(sb + off, Bp + (size_t)(n0 + row) * ldB + kb + cs * 8);
        }
    };

    load_chunk(0);
    asm volatile("cp.async.commit_group;" ::: "memory");
    load_chunk(1);
    asm volatile("cp.async.commit_group;" ::: "memory");

    // fragment addresses (fixed per thread)
    uint32_t a_off[4], b_off[2];
    #pragma unroll
    for (int mi = 0; mi < 4; mi++) {
        int row = wm * 64 + mi * 16 + (lane & 15);
        a_off[mi] = (uint32_t)(row * 144 + ((lane >> 4) * 8) * 2);
    }
    #pragma unroll
    for (int nb = 0; nb < 2; nb++) {
        int row = wn * 32 + nb * 16 + ((lane >> 4) << 3) + (lane & 7);
        b_off[nb] = (uint32_t)(row * 144 + ((((lane >> 3) & 1) << 3)) * 2);
    }

    for (int i = 0; i < nch; i++) {
        if (i < nch - 1) asm volatile("cp.async.wait_group 1;" ::: "memory");
        else             asm volatile("cp.async.wait_group 0;" ::: "memory");
        __syncthreads();
        if (i + 2 < nch) {
            load_chunk(i + 2);
            asm volatile("cp.async.commit_group;" ::: "memory");
        }

        uint32_t sa = base + (i % 3) * STG;
        uint32_t sb = sa + STG_A;

        uint32_t afr[2][4][4], bfr[2][2][4];
        // prefetch kk=0
        #pragma unroll
        for (int mi = 0; mi < 4; mi++) ldsm4(afr[0][mi], sa + a_off[mi]);
        #pragma unroll
        for (int nb = 0; nb < 2; nb++) ldsm4(bfr[0][nb], sb + b_off[nb]);

        #pragma unroll
        for (int kk = 0; kk < 4; kk++) {
            int cur = kk & 1, nxt = cur ^ 1;
            if (kk < 3) {
                uint32_t ko = (uint32_t)((kk + 1) * 32);
                #pragma unroll
                for (int mi = 0; mi < 4; mi++) ldsm4(afr[nxt][mi], sa + a_off[mi] + ko);
                #pragma unroll
                for (int nb = 0; nb < 2; nb++) ldsm4(bfr[nxt][nb], sb + b_off[nb] + ko);
            }
            #pragma unroll
            for (int mi = 0; mi < 4; mi++)
                #pragma unroll
                for (int ni = 0; ni < 4; ni++)
                    mma16816(acc[mi][ni], afr[cur][mi],
                             bfr[cur][ni >> 1][(ni & 1) * 2], bfr[cur][ni >> 1][(ni & 1) * 2 + 1]);
        }
    }

    // ---------------- epilogue ----------------
    int r4 = lane >> 2;
    int c2 = lane & 3;
    float* of = outF32 ? outF32 + (size_t)bz * strideD : nullptr;
    bf16* ohp = outHi ? outHi + (size_t)bz * strideD : nullptr;
    bf16* olp = outLo ? outLo + (size_t)bz * strideD : nullptr;
    const float* rp = resid ? resid + (size_t)bz * strideD : nullptr;

    #pragma unroll
    for (int mi = 0; mi < 4; mi++) {
        #pragma unroll
        for (int half = 0; half < 2; half++) {
            int m = m0 + wm * 64 + mi * 16 + half * 8 + r4;
            float brow = biasRow ? biasRow[m] : 0.f;
            #pragma unroll
            for (int ni = 0; ni < 4; ni++) {
                int n = n0 + wn * 32 + ni * 8 + c2 * 2;
                float v0 = acc[mi][ni][half * 2 + 0] * scale + brow;
                float v1 = acc[mi][ni][half * 2 + 1] * scale + brow;
                if (biasCol) {
                    const float* bc = (biasCol2 && n >= 512) ? biasCol2 - 512 : biasCol;
                    v0 += bc[n]; v1 += bc[n + 1];
                }
                size_t off = (size_t)m * ldD + n;
                if (rp) {
                    float2 q = *(const float2*)(rp + off);
                    v0 += q.x; v1 += q.y;
                }
                if (of) *(float2*)(of + off) = make_float2(v0, v1);
                if (ohp) {
                    bf16 h0, l0, h1, l1;
                    splitf(v0, h0, l0); splitf(v1, h1, l1);
                    *(uint32_t*)(ohp + off) = pack2(h0, h1);
                    *(uint32_t*)(olp + off) = pack2(l0, l1);
                }
            }
        }
    }
}

// ---------------- launch ----------------
extern "C" void kernel_launch(void* const* d_in, const int* in_sizes, int n_in,
                              void* d_out, int out_size) {
    const float* x     = (const float*)d_in[0];
    const float* gamma = (const float*)d_in[1];
    const float* beta  = (const float*)d_in[2];
    const float* wq    = (const float*)d_in[3];
    const float* bq    = (const float*)d_in[4];
    const float* wk    = (const float*)d_in[5];
    const float* bk    = (const float*)d_in[6];
    const float* wv    = (const float*)d_in[7];
    const float* bv    = (const float*)d_in[8];
    const float* wp    = (const float*)d_in[9];
    const float* bp    = (const float*)d_in[10];
    float* out = (float*)d_out;

    bf16 *hthi, *htlo, *whi, *wlo, *qkhi, *qklo, *vhi, *vlo, *ohi, *olo, *ahi, *alo;
    float* ps;
    cudaGetSymbolAddress((void**)&hthi, g_ht_hi); cudaGetSymbolAddress((void**)&htlo, g_ht_lo);
    cudaGetSymbolAddress((void**)&whi, g_w_hi);   cudaGetSymbolAddress((void**)&wlo, g_w_lo);
    cudaGetSymbolAddress((void**)&qkhi, g_qk_hi); cudaGetSymbolAddress((void**)&qklo, g_qk_lo);
    cudaGetSymbolAddress((void**)&vhi, g_v_hi);   cudaGetSymbolAddress((void**)&vlo, g_v_lo);
    cudaGetSymbolAddress((void**)&ohi, g_o_hi);   cudaGetSymbolAddress((void**)&olo, g_o_lo);
    cudaGetSymbolAddress((void**)&ahi, g_a_hi);   cudaGetSymbolAddress((void**)&alo, g_a_lo);
    cudaGetSymbolAddress((void**)&ps, g_s);

    const int SMEM_DYN = 3 * STG;    // 108 KB
    cudaFuncSetAttribute(gemm_hmma, cudaFuncAttributeMaxDynamicSharedMemorySize, SMEM_DYN);

    wconv_kernel<<<4 * (int)(WS / 256), 256>>>(wq, wk, wv, wp, whi, wlo);
    gn_kernel<<<64, 256>>>(x, gamma, beta, hthi, htlo);

    // QK fused: D[4096,1024] = hT @ [wq;wk]^T
    gemm_hmma<<<dim3(1024 / 128, NPX / 128, 2), 256, SMEM_DYN>>>(
        hthi, htlo, CCH, NH, whi, wlo, CCH, 0, CCH,
        nullptr, qkhi, qklo, 1024, NQK, 1.0f, nullptr, bq, bk, nullptr);

    // V = Wv @ hT^T : [512,4096], biasRow=bv
    gemm_hmma<<<dim3(NPX / 128, CCH / 128, 2), 256, SMEM_DYN>>>(
        whi + 2 * WS, wlo + 2 * WS, CCH, 0, hthi, htlo, CCH, NH, CCH,
        nullptr, vhi, vlo, NPX, NH, 1.0f, bv, nullptr, nullptr, nullptr);

    // scores = scale * Q @ K^T : fp32 [4096,4096]
    const float scale = 1.0f / sqrtf((float)CCH);
    gemm_hmma<<<dim3(NPX / 128, NPX / 128, 2), 256, SMEM_DYN>>>(
        qkhi, qklo, 1024, NQK, qkhi + 512, qklo + 512, 1024, NQK, CCH,
        ps, nullptr, nullptr, NPX, NN, scale, nullptr, nullptr, nullptr, nullptr);

    softmax_kernel<<<2 * NPX, 256>>>(ps, ahi, alo);

    // O = attn @ V^T : [4096,512]
    gemm_hmma<<<dim3(CCH / 128, NPX / 128, 2), 256, SMEM_DYN>>>(
        ahi, alo, NPX, NN, vhi, vlo, NPX, NH, NPX,
        nullptr, ohi, olo, CCH, NH, 1.0f, nullptr, nullptr, nullptr, nullptr);

    // out = x + Wp @ O^T + bp : fp32 [512,4096]
    gemm_hmma<<<dim3(NPX / 128, CCH / 128, 2), 256, SMEM_DYN>>>(
        whi + 3 * WS, wlo + 3 * WS, CCH, 0, ohi, olo, CCH, NH, CCH,
        out, nullptr, nullptr, NPX, (size_t)CCH * NPX, 1.0f, bp, nullptr, nullptr, x);
}

// round 5
// speedup vs baseline: 2.6224x; 1.0370x over previous
#include <cuda_runtime.h>
#include <cuda_bf16.h>
#include <math.h>
#include <stdint.h>

#define CCH 512
#define NPX 4096
typedef __nv_bfloat16 bf16;

static const size_t NH  = (size_t)NPX * CCH;
static const size_t NN  = (size_t)NPX * NPX;
static const size_t NQK = (size_t)NPX * 1024;
#define WS ((size_t)CCH * CCH)

// ---------------- static scratch ----------------
__device__ bf16 g_ht_hi[(size_t)2 * NPX * CCH];
__device__ bf16 g_ht_lo[(size_t)2 * NPX * CCH];
__device__ bf16 g_w_hi[(size_t)4 * CCH * CCH];
__device__ bf16 g_w_lo[(size_t)4 * CCH * CCH];
__device__ bf16 g_qk_hi[(size_t)2 * NPX * 1024];
__device__ bf16 g_qk_lo[(size_t)2 * NPX * 1024];
__device__ bf16 g_v_hi[(size_t)2 * CCH * NPX];
__device__ bf16 g_v_lo[(size_t)2 * CCH * NPX];
__device__ bf16 g_o_hi[(size_t)2 * NPX * CCH];
__device__ bf16 g_o_lo[(size_t)2 * NPX * CCH];
__device__ float g_s[(size_t)2 * NPX * NPX];
__device__ bf16 g_a_hi[(size_t)2 * NPX * NPX];
__device__ bf16 g_a_lo[(size_t)2 * NPX * NPX];

// ---------------- helpers ----------------
__device__ __forceinline__ uint32_t smem_u32(const void* p) {
    uint32_t a;
    asm("{ .reg .u64 t; cvta.to.shared.u64 t, %1; cvt.u32.u64 %0, t; }" : "=r"(a) : "l"(p));
    return a;
}
__device__ __forceinline__ void splitf(float v, bf16& h, bf16& l) {
    h = __float2bfloat16(v);
    l = __float2bfloat16(v - __bfloat162float(h));
}
__device__ __forceinline__ uint32_t pack2(bf16 a, bf16 b) {
    __nv_bfloat162 t; t.x = a; t.y = b;
    return *reinterpret_cast<uint32_t*>(&t);
}
__device__ __forceinline__ void cp16(uint32_t s, const void* g) {
    asm volatile("cp.async.cg.shared.global [%0], [%1], 16;" :: "r"(s), "l"(g));
}
__device__ __forceinline__ void ldsm4(uint32_t* r, uint32_t addr) {
    asm volatile("ldmatrix.sync.aligned.m8n8.x4.shared.b16 {%0,%1,%2,%3}, [%4];"
        : "=r"(r[0]), "=r"(r[1]), "=r"(r[2]), "=r"(r[3]) : "r"(addr));
}
__device__ __forceinline__ void mma16816(float* d, const uint32_t* a, uint32_t b0, uint32_t b1) {
    asm volatile("mma.sync.aligned.m16n8k16.row.col.f32.bf16.bf16.f32 "
        "{%0,%1,%2,%3}, {%4,%5,%6,%7}, {%8,%9}, {%0,%1,%2,%3};"
        : "+f"(d[0]), "+f"(d[1]), "+f"(d[2]), "+f"(d[3])
        : "r"(a[0]), "r"(a[1]), "r"(a[2]), "r"(a[3]), "r"(b0), "r"(b1));
}

// ---------------- weight split ----------------
__global__ void __launch_bounds__(256) wconv_kernel(const float* __restrict__ w0,
                                                    const float* __restrict__ w1,
                                                    const float* __restrict__ w2,
                                                    const float* __restrict__ w3,
                                                    bf16* __restrict__ hi, bf16* __restrict__ lo) {
    size_t i = (size_t)blockIdx.x * 256 + threadIdx.x;
    size_t which = i / WS, r = i - which * WS;
    const float* w = (which == 0) ? w0 : (which == 1) ? w1 : (which == 2) ? w2 : w3;
    float v = w[r];
    bf16 h, l; splitf(v, h, l);
    hi[i] = h; lo[i] = l;
}

// ---------------- GroupNorm + transpose + split ----------------
__global__ void __launch_bounds__(256) gn_kernel(const float* __restrict__ x,
                                                 const float* __restrict__ gamma,
                                                 const float* __restrict__ beta,
                                                 bf16* __restrict__ hthi, bf16* __restrict__ htlo) {
    int b = blockIdx.x >> 5;
    int g = blockIdx.x & 31;
    const size_t base = ((size_t)b * CCH + (size_t)g * 16) * NPX;
    const float4* xp = (const float4*)(x + base);
    const int TOT4 = 16 * NPX / 4;
    int tid = threadIdx.x;

    float s = 0.f, ss = 0.f;
    for (int i = tid; i < TOT4; i += 256) {
        float4 v = xp[i];
        s  += v.x + v.y + v.z + v.w;
        ss += v.x * v.x + v.y * v.y + v.z * v.z + v.w * v.w;
    }
    __shared__ float rs[8], rss[8];
    #pragma unroll
    for (int o = 16; o > 0; o >>= 1) {
        s  += __shfl_xor_sync(0xffffffffu, s, o);
        ss += __shfl_xor_sync(0xffffffffu, ss, o);
    }
    if ((tid & 31) == 0) { rs[tid >> 5] = s; rss[tid >> 5] = ss; }
    __syncthreads();
    float S = 0.f, SS = 0.f;
    #pragma unroll
    for (int w = 0; w < 8; w++) { S += rs[w]; SS += rss[w]; }
    const float inv_cnt = 1.0f / (float)(16 * NPX);
    float mean = S * inv_cnt;
    float var  = SS * inv_cnt - mean * mean;
    float rstd = rsqrtf(var + 1e-6f);

    __shared__ float sga[16], sbe[16];
    if (tid < 16) {
        int c = g * 16 + tid;
        float ga = gamma[c] * rstd;
        sga[tid] = ga;
        sbe[tid] = beta[c] - mean * ga;
    }
    __shared__ float xs[16][256];
    __syncthreads();

    for (int p0 = 0; p0 < NPX; p0 += 256) {
        #pragma unroll
        for (int c = 0; c < 16; c++) xs[c][tid] = x[base + (size_t)c * NPX + p0 + tid];
        __syncthreads();
        uint32_t hw[8], lw[8];
        #pragma unroll
        for (int c2 = 0; c2 < 8; c2++) {
            float v0 = xs[2 * c2][tid]     * sga[2 * c2]     + sbe[2 * c2];
            float v1 = xs[2 * c2 + 1][tid] * sga[2 * c2 + 1] + sbe[2 * c2 + 1];
            bf16 h0, l0, h1, l1;
            splitf(v0, h0, l0); splitf(v1, h1, l1);
            hw[c2] = pack2(h0, h1); lw[c2] = pack2(l0, l1);
        }
        size_t o = ((size_t)b * NPX + p0 + tid) * CCH + g * 16;
        ((uint4*)(hthi + o))[0] = make_uint4(hw[0], hw[1], hw[2], hw[3]);
        ((uint4*)(hthi + o))[1] = make_uint4(hw[4], hw[5], hw[6], hw[7]);
        ((uint4*)(htlo + o))[0] = make_uint4(lw[0], lw[1], lw[2], lw[3]);
        ((uint4*)(htlo + o))[1] = make_uint4(lw[4], lw[5], lw[6], lw[7]);
        __syncthreads();
    }
}

// ---------------- softmax fp32 -> bf16 hi/lo ----------------
__global__ void __launch_bounds__(256) softmax_kernel(const float* __restrict__ S,
                                                      bf16* __restrict__ ahi, bf16* __restrict__ alo) {
    size_t row = blockIdx.x;
    const float* p = S + row * NPX;
    int tid = threadIdx.x;
    float2 r[8];
    float m = -1e30f;
    #pragma unroll
    for (int i = 0; i < 8; i++) {
        r[i] = *(const float2*)(p + tid * 2 + i * 512);
        m = fmaxf(m, fmaxf(r[i].x, r[i].y));
    }
    __shared__ float red[8];
    #pragma unroll
    for (int o = 16; o > 0; o >>= 1) m = fmaxf(m, __shfl_xor_sync(0xffffffffu, m, o));
    if ((tid & 31) == 0) red[tid >> 5] = m;
    __syncthreads();
    float bm = red[0];
    #pragma unroll
    for (int w = 1; w < 8; w++) bm = fmaxf(bm, red[w]);
    __syncthreads();
    float s = 0.f;
    #pragma unroll
    for (int i = 0; i < 8; i++) {
        r[i].x = __expf(r[i].x - bm); r[i].y = __expf(r[i].y - bm);
        s += r[i].x + r[i].y;
    }
    #pragma unroll
    for (int o = 16; o > 0; o >>= 1) s += __shfl_xor_sync(0xffffffffu, s, o);
    if ((tid & 31) == 0) red[tid >> 5] = s;
    __syncthreads();
    float bs = 0.f;
    #pragma unroll
    for (int w = 0; w < 8; w++) bs += red[w];
    float inv = 1.0f / bs;
    #pragma unroll
    for (int i = 0; i < 8; i++) {
        float v0 = r[i].x * inv, v1 = r[i].y * inv;
        bf16 h0, l0, h1, l1;
        splitf(v0, h0, l0); splitf(v1, h1, l1);
        size_t idx = row * NPX + tid * 2 + i * 512;
        *(uint32_t*)(ahi + idx) = pack2(h0, h1);
        *(uint32_t*)(alo + idx) = pack2(l0, l1);
    }
}

// ---------------- bf16x3 HMMA GEMM ----------------
// CTA tile 128x256, warp tile 64x64 (2x4 warps), BK=64, 3-stage, 1 sync/chunk.
#define ROWB  144                    // padded row bytes (64 elems + 8 pad)
#define STG_A (128 * ROWB)           // 18432
#define STG_B (256 * ROWB)           // 36864
#define STG   (STG_A + STG_B)        // 55296
__global__ void gemm_hmma(
    const bf16* __restrict__ Ahi, const bf16* __restrict__ Alo, int ldA, size_t strideA,
    const bf16* __restrict__ Bhi, const bf16* __restrict__ Blo, int ldB, size_t strideB,
    int K,
    float* __restrict__ outF32, bf16* __restrict__ outHi, bf16* __restrict__ outLo,
    int ldD, size_t strideD,
    float scale,
    const float* __restrict__ biasRow,
    const float* __restrict__ biasCol, const float* __restrict__ biasCol2,
    const float* __restrict__ resid)
{
    extern __shared__ char smemraw[];
    int tid = threadIdx.x, wid = tid >> 5, lane = tid & 31;
    int m0 = blockIdx.y * 128, n0 = blockIdx.x * 256, bz = blockIdx.z;
    Ahi += (size_t)bz * strideA; Alo += (size_t)bz * strideA;
    Bhi += (size_t)bz * strideB; Blo += (size_t)bz * strideB;

    uint32_t base = smem_u32(smemraw);
    int wm = wid & 1, wn = wid >> 1;     // 2 x 4 warp grid

    const int kc_per = K >> 6;
    const int nch = 3 * kc_per;

    float acc[4][8][4];
    #pragma unroll
    for (int a = 0; a < 4; a++)
        #pragma unroll
        for (int b = 0; b < 8; b++)
            #pragma unroll
            for (int c = 0; c < 4; c++) acc[a][b][c] = 0.f;

    auto load_chunk = [&](int i) {
        int st = i % 3;
        int seg = i / kc_per;
        int kc = i - seg * kc_per;
        const bf16* Ap = (seg < 2) ? Ahi : Alo;
        const bf16* Bp = (seg == 1) ? Blo : Bhi;
        size_t kb = (size_t)kc * 64;
        uint32_t sa = base + st * STG;
        uint32_t sb = sa + STG_A;
        #pragma unroll
        for (int r = 0; r < 4; r++) {       // A: 128 rows x 8 slots = 1024
            int u = tid + r * 256;
            int row = u >> 3, cs = u & 7;
            cp16(sa + (uint32_t)(row * ROWB + cs * 16),
                 Ap + (size_t)(m0 + row) * ldA + kb + cs * 8);
        }
        #pragma unroll
        for (int r = 0; r < 8; r++) {       // B: 256 rows x 8 slots = 2048
            int u = tid + r * 256;
            int row = u >> 3, cs = u & 7;
            cp16(sb + (uint32_t)(row * ROWB + cs * 16),
                 Bp + (size_t)(n0 + row) * ldB + kb + cs * 8);
        }
    };

    load_chunk(0);
    asm volatile("cp.async.commit_group;" ::: "memory");
    load_chunk(1);
    asm volatile("cp.async.commit_group;" ::: "memory");

    uint32_t a_off[4], b_off[4];
    #pragma unroll
    for (int mi = 0; mi < 4; mi++) {
        int row = wm * 64 + mi * 16 + (lane & 15);
        a_off[mi] = (uint32_t)(row * ROWB + ((lane >> 4) * 8) * 2);
    }
    #pragma unroll
    for (int nb = 0; nb < 4; nb++) {
        int row = wn * 64 + nb * 16 + ((lane >> 4) << 3) + (lane & 7);
        b_off[nb] = (uint32_t)(row * ROWB + ((((lane >> 3) & 1) << 3)) * 2);
    }

    for (int i = 0; i < nch; i++) {
        if (i < nch - 1) asm volatile("cp.async.wait_group 1;" ::: "memory");
        else             asm volatile("cp.async.wait_group 0;" ::: "memory");
        __syncthreads();
        if (i + 2 < nch) {
            load_chunk(i + 2);
            asm volatile("cp.async.commit_group;" ::: "memory");
        }

        uint32_t sa = base + (i % 3) * STG;
        uint32_t sb = sa + STG_A;

        uint32_t afr[2][4][4], bfr[2][4][4];
        #pragma unroll
        for (int mi = 0; mi < 4; mi++) ldsm4(afr[0][mi], sa + a_off[mi]);
        #pragma unroll
        for (int nb = 0; nb < 4; nb++) ldsm4(bfr[0][nb], sb + b_off[nb]);

        #pragma unroll
        for (int kk = 0; kk < 4; kk++) {
            int cur = kk & 1, nxt = cur ^ 1;
            if (kk < 3) {
                uint32_t ko = (uint32_t)((kk + 1) * 32);
                #pragma unroll
                for (int mi = 0; mi < 4; mi++) ldsm4(afr[nxt][mi], sa + a_off[mi] + ko);
                #pragma unroll
                for (int nb = 0; nb < 4; nb++) ldsm4(bfr[nxt][nb], sb + b_off[nb] + ko);
            }
            #pragma unroll
            for (int mi = 0; mi < 4; mi++)
                #pragma unroll
                for (int ni = 0; ni < 8; ni++)
                    mma16816(acc[mi][ni], afr[cur][mi],
                             bfr[cur][ni >> 1][(ni & 1) * 2], bfr[cur][ni >> 1][(ni & 1) * 2 + 1]);
        }
    }

    // ---------------- epilogue ----------------
    int r4 = lane >> 2;
    int c2 = lane & 3;
    float* of = outF32 ? outF32 + (size_t)bz * strideD : nullptr;
    bf16* ohp = outHi ? outHi + (size_t)bz * strideD : nullptr;
    bf16* olp = outLo ? outLo + (size_t)bz * strideD : nullptr;
    const float* rp = resid ? resid + (size_t)bz * strideD : nullptr;

    #pragma unroll
    for (int mi = 0; mi < 4; mi++) {
        #pragma unroll
        for (int half = 0; half < 2; half++) {
            int m = m0 + wm * 64 + mi * 16 + half * 8 + r4;
            float brow = biasRow ? biasRow[m] : 0.f;
            #pragma unroll
            for (int ni = 0; ni < 8; ni++) {
                int n = n0 + wn * 64 + ni * 8 + c2 * 2;
                float v0 = acc[mi][ni][half * 2 + 0] * scale + brow;
                float v1 = acc[mi][ni][half * 2 + 1] * scale + brow;
                if (biasCol) {
                    const float* bc = (biasCol2 && n >= 512) ? biasCol2 - 512 : biasCol;
                    v0 += bc[n]; v1 += bc[n + 1];
                }
                size_t off = (size_t)m * ldD + n;
                if (rp) {
                    float2 q = *(const float2*)(rp + off);
                    v0 += q.x; v1 += q.y;
                }
                if (of) *(float2*)(of + off) = make_float2(v0, v1);
                if (ohp) {
                    bf16 h0, l0, h1, l1;
                    splitf(v0, h0, l0); splitf(v1, h1, l1);
                    *(uint32_t*)(ohp + off) = pack2(h0, h1);
                    *(uint32_t*)(olp + off) = pack2(l0, l1);
                }
            }
        }
    }
}

// ---------------- launch ----------------
extern "C" void kernel_launch(void* const* d_in, const int* in_sizes, int n_in,
                              void* d_out, int out_size) {
    const float* x     = (const float*)d_in[0];
    const float* gamma = (const float*)d_in[1];
    const float* beta  = (const float*)d_in[2];
    const float* wq    = (const float*)d_in[3];
    const float* bq    = (const float*)d_in[4];
    const float* wk    = (const float*)d_in[5];
    const float* bk    = (const float*)d_in[6];
    const float* wv    = (const float*)d_in[7];
    const float* bv    = (const float*)d_in[8];
    const float* wp    = (const float*)d_in[9];
    const float* bp    = (const float*)d_in[10];
    float* out = (float*)d_out;

    bf16 *hthi, *htlo, *whi, *wlo, *qkhi, *qklo, *vhi, *vlo, *ohi, *olo, *ahi, *alo;
    float* ps;
    cudaGetSymbolAddress((void**)&hthi, g_ht_hi); cudaGetSymbolAddress((void**)&htlo, g_ht_lo);
    cudaGetSymbolAddress((void**)&whi, g_w_hi);   cudaGetSymbolAddress((void**)&wlo, g_w_lo);
    cudaGetSymbolAddress((void**)&qkhi, g_qk_hi); cudaGetSymbolAddress((void**)&qklo, g_qk_lo);
    cudaGetSymbolAddress((void**)&vhi, g_v_hi);   cudaGetSymbolAddress((void**)&vlo, g_v_lo);
    cudaGetSymbolAddress((void**)&ohi, g_o_hi);   cudaGetSymbolAddress((void**)&olo, g_o_lo);
    cudaGetSymbolAddress((void**)&ahi, g_a_hi);   cudaGetSymbolAddress((void**)&alo, g_a_lo);
    cudaGetSymbolAddress((void**)&ps, g_s);

    const int SMEM_DYN = 3 * STG;    // 162 KB
    cudaFuncSetAttribute(gemm_hmma, cudaFuncAttributeMaxDynamicSharedMemorySize, SMEM_DYN);

    wconv_kernel<<<4 * (int)(WS / 256), 256>>>(wq, wk, wv, wp, whi, wlo);
    gn_kernel<<<64, 256>>>(x, gamma, beta, hthi, htlo);

    // QK fused: D[4096,1024] = hT @ [wq;wk]^T
    gemm_hmma<<<dim3(1024 / 256, NPX / 128, 2), 256, SMEM_DYN>>>(
        hthi, htlo, CCH, NH, whi, wlo, CCH, 0, CCH,
        nullptr, qkhi, qklo, 1024, NQK, 1.0f, nullptr, bq, bk, nullptr);

    // V = Wv @ hT^T : [512,4096], biasRow=bv
    gemm_hmma<<<dim3(NPX / 256, CCH / 128, 2), 256, SMEM_DYN>>>(
        whi + 2 * WS, wlo + 2 * WS, CCH, 0, hthi, htlo, CCH, NH, CCH,
        nullptr, vhi, vlo, NPX, NH, 1.0f, bv, nullptr, nullptr, nullptr);

    // scores = scale * Q @ K^T : fp32 [4096,4096]
    const float scale = 1.0f / sqrtf((float)CCH);
    gemm_hmma<<<dim3(NPX / 256, NPX / 128, 2), 256, SMEM_DYN>>>(
        qkhi, qklo, 1024, NQK, qkhi + 512, qklo + 512, 1024, NQK, CCH,
        ps, nullptr, nullptr, NPX, NN, scale, nullptr, nullptr, nullptr, nullptr);

    softmax_kernel<<<2 * NPX, 256>>>(ps, ahi, alo);

    // O = attn @ V^T : [4096,512]
    gemm_hmma<<<dim3(CCH / 256, NPX / 128, 2), 256, SMEM_DYN>>>(
        ahi, alo, NPX, NN, vhi, vlo, NPX, NH, NPX,
        nullptr, ohi, olo, CCH, NH, 1.0f, nullptr, nullptr, nullptr, nullptr);

    // out = x + Wp @ O^T + bp : fp32 [512,4096]
    gemm_hmma<<<dim3(NPX / 256, CCH / 128, 2), 256, SMEM_DYN>>>(
        whi + 3 * WS, wlo + 3 * WS, CCH, 0, ohi, olo, CCH, NH, CCH,
        out, nullptr, nullptr, NPX, (size_t)CCH * NPX, 1.0f, bp, nullptr, nullptr, x);
}

// round 6
// speedup vs baseline: 4.9814x; 1.8996x over previous
#include <cuda_runtime.h>
#include <cuda_fp16.h>
#include <math.h>
#include <stdint.h>

#define CCH 512
#define NPX 4096
typedef __half fp16;

static const size_t NH  = (size_t)NPX * CCH;
static const size_t NN  = (size_t)NPX * NPX;
static const size_t NQK = (size_t)NPX * 1024;
#define WS ((size_t)CCH * CCH)

// ---------------- static scratch ----------------
__device__ fp16 g_ht_hi[(size_t)2 * NPX * CCH];   // GN output [B][N][C]
__device__ fp16 g_ht_lo[(size_t)2 * NPX * CCH];
__device__ fp16 g_w_hi[(size_t)4 * CCH * CCH];
__device__ fp16 g_w_lo[(size_t)4 * CCH * CCH];
__device__ fp16 g_qk[(size_t)2 * NPX * 1024];     // Q cols 0-511, K cols 512-1023 (single fp16)
__device__ fp16 g_v[(size_t)2 * CCH * NPX];       // [B][C][N] single fp16
__device__ fp16 g_o_hi[(size_t)2 * NPX * CCH];    // [B][N][C]
__device__ fp16 g_o_lo[(size_t)2 * NPX * CCH];
__device__ float g_s[(size_t)2 * NPX * NPX];
__device__ fp16 g_a[(size_t)2 * NPX * NPX];       // attn single fp16

// ---------------- helpers ----------------
__device__ __forceinline__ uint32_t smem_u32(const void* p) {
    uint32_t a;
    asm("{ .reg .u64 t; cvta.to.shared.u64 t, %1; cvt.u32.u64 %0, t; }" : "=r"(a) : "l"(p));
    return a;
}
__device__ __forceinline__ void splitf(float v, fp16& h, fp16& l) {
    h = __float2half(v);
    l = __float2half(v - __half2float(h));
}
__device__ __forceinline__ uint32_t pack2(fp16 a, fp16 b) {
    __half2 t; t.x = a; t.y = b;
    return *reinterpret_cast<uint32_t*>(&t);
}
__device__ __forceinline__ void cp16(uint32_t s, const void* g) {
    asm volatile("cp.async.cg.shared.global [%0], [%1], 16;" :: "r"(s), "l"(g));
}
__device__ __forceinline__ void ldsm4(uint32_t* r, uint32_t addr) {
    asm volatile("ldmatrix.sync.aligned.m8n8.x4.shared.b16 {%0,%1,%2,%3}, [%4];"
        : "=r"(r[0]), "=r"(r[1]), "=r"(r[2]), "=r"(r[3]) : "r"(addr));
}
__device__ __forceinline__ void mma16816(float* d, const uint32_t* a, uint32_t b0, uint32_t b1) {
    asm volatile("mma.sync.aligned.m16n8k16.row.col.f32.f16.f16.f32 "
        "{%0,%1,%2,%3}, {%4,%5,%6,%7}, {%8,%9}, {%0,%1,%2,%3};"
        : "+f"(d[0]), "+f"(d[1]), "+f"(d[2]), "+f"(d[3])
        : "r"(a[0]), "r"(a[1]), "r"(a[2]), "r"(a[3]), "r"(b0), "r"(b1));
}

// ---------------- weight split ----------------
__global__ void __launch_bounds__(256) wconv_kernel(const float* __restrict__ w0,
                                                    const float* __restrict__ w1,
                                                    const float* __restrict__ w2,
                                                    const float* __restrict__ w3,
                                                    fp16* __restrict__ hi, fp16* __restrict__ lo) {
    size_t i = (size_t)blockIdx.x * 256 + threadIdx.x;
    size_t which = i / WS, r = i - which * WS;
    const float* w = (which == 0) ? w0 : (which == 1) ? w1 : (which == 2) ? w2 : w3;
    float v = w[r];
    fp16 h, l; splitf(v, h, l);
    hi[i] = h; lo[i] = l;
}

// ---------------- GroupNorm + transpose + split ----------------
__global__ void __launch_bounds__(256) gn_kernel(const float* __restrict__ x,
                                                 const float* __restrict__ gamma,
                                                 const float* __restrict__ beta,
                                                 fp16* __restrict__ hthi, fp16* __restrict__ htlo) {
    int b = blockIdx.x >> 5;
    int g = blockIdx.x & 31;
    const size_t base = ((size_t)b * CCH + (size_t)g * 16) * NPX;
    const float4* xp = (const float4*)(x + base);
    const int TOT4 = 16 * NPX / 4;
    int tid = threadIdx.x;

    float s = 0.f, ss = 0.f;
    for (int i = tid; i < TOT4; i += 256) {
        float4 v = xp[i];
        s  += v.x + v.y + v.z + v.w;
        ss += v.x * v.x + v.y * v.y + v.z * v.z + v.w * v.w;
    }
    __shared__ float rs[8], rss[8];
    #pragma unroll
    for (int o = 16; o > 0; o >>= 1) {
        s  += __shfl_xor_sync(0xffffffffu, s, o);
        ss += __shfl_xor_sync(0xffffffffu, ss, o);
    }
    if ((tid & 31) == 0) { rs[tid >> 5] = s; rss[tid >> 5] = ss; }
    __syncthreads();
    float S = 0.f, SS = 0.f;
    #pragma unroll
    for (int w = 0; w < 8; w++) { S += rs[w]; SS += rss[w]; }
    const float inv_cnt = 1.0f / (float)(16 * NPX);
    float mean = S * inv_cnt;
    float var  = SS * inv_cnt - mean * mean;
    float rstd = rsqrtf(var + 1e-6f);

    __shared__ float sga[16], sbe[16];
    if (tid < 16) {
        int c = g * 16 + tid;
        float ga = gamma[c] * rstd;
        sga[tid] = ga;
        sbe[tid] = beta[c] - mean * ga;
    }
    __shared__ float xs[16][256];
    __syncthreads();

    for (int p0 = 0; p0 < NPX; p0 += 256) {
        #pragma unroll
        for (int c = 0; c < 16; c++) xs[c][tid] = x[base + (size_t)c * NPX + p0 + tid];
        __syncthreads();
        uint32_t hw[8], lw[8];
        #pragma unroll
        for (int c2 = 0; c2 < 8; c2++) {
            float v0 = xs[2 * c2][tid]     * sga[2 * c2]     + sbe[2 * c2];
            float v1 = xs[2 * c2 + 1][tid] * sga[2 * c2 + 1] + sbe[2 * c2 + 1];
            fp16 h0, l0, h1, l1;
            splitf(v0, h0, l0); splitf(v1, h1, l1);
            hw[c2] = pack2(h0, h1); lw[c2] = pack2(l0, l1);
        }
        size_t o = ((size_t)b * NPX + p0 + tid) * CCH + g * 16;
        ((uint4*)(hthi + o))[0] = make_uint4(hw[0], hw[1], hw[2], hw[3]);
        ((uint4*)(hthi + o))[1] = make_uint4(hw[4], hw[5], hw[6], hw[7]);
        ((uint4*)(htlo + o))[0] = make_uint4(lw[0], lw[1], lw[2], lw[3]);
        ((uint4*)(htlo + o))[1] = make_uint4(lw[4], lw[5], lw[6], lw[7]);
        __syncthreads();
    }
}

// ---------------- softmax fp32 -> single fp16 ----------------
__global__ void __launch_bounds__(256) softmax_kernel(const float* __restrict__ S,
                                                      fp16* __restrict__ a) {
    size_t row = blockIdx.x;
    const float* p = S + row * NPX;
    int tid = threadIdx.x;
    float2 r[8];
    float m = -1e30f;
    #pragma unroll
    for (int i = 0; i < 8; i++) {
        r[i] = *(const float2*)(p + tid * 2 + i * 512);
        m = fmaxf(m, fmaxf(r[i].x, r[i].y));
    }
    __shared__ float red[8];
    #pragma unroll
    for (int o = 16; o > 0; o >>= 1) m = fmaxf(m, __shfl_xor_sync(0xffffffffu, m, o));
    if ((tid & 31) == 0) red[tid >> 5] = m;
    __syncthreads();
    float bm = red[0];
    #pragma unroll
    for (int w = 1; w < 8; w++) bm = fmaxf(bm, red[w]);
    __syncthreads();
    float s = 0.f;
    #pragma unroll
    for (int i = 0; i < 8; i++) {
        r[i].x = __expf(r[i].x - bm); r[i].y = __expf(r[i].y - bm);
        s += r[i].x + r[i].y;
    }
    #pragma unroll
    for (int o = 16; o > 0; o >>= 1) s += __shfl_xor_sync(0xffffffffu, s, o);
    if ((tid & 31) == 0) red[tid >> 5] = s;
    __syncthreads();
    float bs = 0.f;
    #pragma unroll
    for (int w = 0; w < 8; w++) bs += red[w];
    float inv = 1.0f / bs;
    #pragma unroll
    for (int i = 0; i < 8; i++) {
        size_t idx = row * NPX + tid * 2 + i * 512;
        *(uint32_t*)(a + idx) = pack2(__float2half(r[i].x * inv), __float2half(r[i].y * inv));
    }
}

// ---------------- fp16 HMMA GEMM (1 or 3 passes) ----------------
// CTA tile 128x256, warp tile 64x64, BK=64, 3-stage cp.async.
#define ROWB  144
#define STG_A (128 * ROWB)
#define STG_B (256 * ROWB)
#define STG   (STG_A + STG_B)
__global__ void gemm_hmma(
    const fp16* __restrict__ Ahi, const fp16* __restrict__ Alo, int ldA, size_t strideA,
    const fp16* __restrict__ Bhi, const fp16* __restrict__ Blo, int ldB, size_t strideB,
    int K, int npass,
    float* __restrict__ outF32, fp16* __restrict__ outH,
    fp16* __restrict__ outHi, fp16* __restrict__ outLo,
    int ldD, size_t strideD,
    float scale,
    const float* __restrict__ biasRow,
    const float* __restrict__ biasCol, const float* __restrict__ biasCol2,
    const float* __restrict__ resid)
{
    extern __shared__ char smemraw[];
    int tid = threadIdx.x, wid = tid >> 5, lane = tid & 31;
    int m0 = blockIdx.y * 128, n0 = blockIdx.x * 256, bz = blockIdx.z;
    Ahi += (size_t)bz * strideA; Alo += (size_t)bz * strideA;
    Bhi += (size_t)bz * strideB; Blo += (size_t)bz * strideB;

    uint32_t base = smem_u32(smemraw);
    int wm = wid & 1, wn = wid >> 1;

    const int kc_per = K >> 6;
    const int nch = npass * kc_per;

    float acc[4][8][4];
    #pragma unroll
    for (int a = 0; a < 4; a++)
        #pragma unroll
        for (int b = 0; b < 8; b++)
            #pragma unroll
            for (int c = 0; c < 4; c++) acc[a][b][c] = 0.f;

    auto load_chunk = [&](int i) {
        int st = i % 3;
        int seg = i / kc_per;
        int kc = i - seg * kc_per;
        const fp16* Ap = (seg < 2) ? Ahi : Alo;
        const fp16* Bp = (seg == 1) ? Blo : Bhi;
        size_t kb = (size_t)kc * 64;
        uint32_t sa = base + st * STG;
        uint32_t sb = sa + STG_A;
        #pragma unroll
        for (int r = 0; r < 4; r++) {
            int u = tid + r * 256;
            int row = u >> 3, cs = u & 7;
            cp16(sa + (uint32_t)(row * ROWB + cs * 16),
                 Ap + (size_t)(m0 + row) * ldA + kb + cs * 8);
        }
        #pragma unroll
        for (int r = 0; r < 8; r++) {
            int u = tid + r * 256;
            int row = u >> 3, cs = u & 7;
            cp16(sb + (uint32_t)(row * ROWB + cs * 16),
                 Bp + (size_t)(n0 + row) * ldB + kb + cs * 8);
        }
    };

    load_chunk(0);
    asm volatile("cp.async.commit_group;" ::: "memory");
    if (nch > 1) load_chunk(1);
    asm volatile("cp.async.commit_group;" ::: "memory");

    uint32_t a_off[4], b_off[4];
    #pragma unroll
    for (int mi = 0; mi < 4; mi++) {
        int row = wm * 64 + mi * 16 + (lane & 15);
        a_off[mi] = (uint32_t)(row * ROWB + ((lane >> 4) * 8) * 2);
    }
    #pragma unroll
    for (int nb = 0; nb < 4; nb++) {
        int row = wn * 64 + nb * 16 + ((lane >> 4) << 3) + (lane & 7);
        b_off[nb] = (uint32_t)(row * ROWB + ((((lane >> 3) & 1) << 3)) * 2);
    }

    for (int i = 0; i < nch; i++) {
        if (i < nch - 1) asm volatile("cp.async.wait_group 1;" ::: "memory");
        else             asm volatile("cp.async.wait_group 0;" ::: "memory");
        __syncthreads();
        if (i + 2 < nch) {
            load_chunk(i + 2);
            asm volatile("cp.async.commit_group;" ::: "memory");
        }

        uint32_t sa = base + (i % 3) * STG;
        uint32_t sb = sa + STG_A;

        uint32_t afr[2][4][4], bfr[2][4][4];
        #pragma unroll
        for (int mi = 0; mi < 4; mi++) ldsm4(afr[0][mi], sa + a_off[mi]);
        #pragma unroll
        for (int nb = 0; nb < 4; nb++) ldsm4(bfr[0][nb], sb + b_off[nb]);

        #pragma unroll
        for (int kk = 0; kk < 4; kk++) {
            int cur = kk & 1, nxt = cur ^ 1;
            if (kk < 3) {
                uint32_t ko = (uint32_t)((kk + 1) * 32);
                #pragma unroll
                for (int mi = 0; mi < 4; mi++) ldsm4(afr[nxt][mi], sa + a_off[mi] + ko);
                #pragma unroll
                for (int nb = 0; nb < 4; nb++) ldsm4(bfr[nxt][nb], sb + b_off[nb] + ko);
            }
            #pragma unroll
            for (int mi = 0; mi < 4; mi++)
                #pragma unroll
                for (int ni = 0; ni < 8; ni++)
                    mma16816(acc[mi][ni], afr[cur][mi],
                             bfr[cur][ni >> 1][(ni & 1) * 2], bfr[cur][ni >> 1][(ni & 1) * 2 + 1]);
        }
    }

    // ---------------- epilogue ----------------
    int r4 = lane >> 2;
    int c2 = lane & 3;
    float* of  = outF32 ? outF32 + (size_t)bz * strideD : nullptr;
    fp16* oh   = outH   ? outH   + (size_t)bz * strideD : nullptr;
    fp16* ohp  = outHi  ? outHi  + (size_t)bz * strideD : nullptr;
    fp16* olp  = outLo  ? outLo  + (size_t)bz * strideD : nullptr;
    const float* rp = resid ? resid + (size_t)bz * strideD : nullptr;

    #pragma unroll
    for (int mi = 0; mi < 4; mi++) {
        #pragma unroll
        for (int half = 0; half < 2; half++) {
            int m = m0 + wm * 64 + mi * 16 + half * 8 + r4;
            float brow = biasRow ? biasRow[m] : 0.f;
            #pragma unroll
            for (int ni = 0; ni < 8; ni++) {
                int n = n0 + wn * 64 + ni * 8 + c2 * 2;
                float v0 = acc[mi][ni][half * 2 + 0] * scale + brow;
                float v1 = acc[mi][ni][half * 2 + 1] * scale + brow;
                if (biasCol) {
                    const float* bc = (biasCol2 && n >= 512) ? biasCol2 - 512 : biasCol;
                    v0 += bc[n]; v1 += bc[n + 1];
                }
                size_t off = (size_t)m * ldD + n;
                if (rp) {
                    float2 q = *(const float2*)(rp + off);
                    v0 += q.x; v1 += q.y;
                }
                if (of) *(float2*)(of + off) = make_float2(v0, v1);
                if (oh) *(uint32_t*)(oh + off) = pack2(__float2half(v0), __float2half(v1));
                if (ohp) {
                    fp16 h0, l0, h1, l1;
                    splitf(v0, h0, l0); splitf(v1, h1, l1);
                    *(uint32_t*)(ohp + off) = pack2(h0, h1);
                    *(uint32_t*)(olp + off) = pack2(l0, l1);
                }
            }
        }
    }
}

// ---------------- launch ----------------
extern "C" void kernel_launch(void* const* d_in, const int* in_sizes, int n_in,
                              void* d_out, int out_size) {
    const float* x     = (const float*)d_in[0];
    const float* gamma = (const float*)d_in[1];
    const float* beta  = (const float*)d_in[2];
    const float* wq    = (const float*)d_in[3];
    const float* bq    = (const float*)d_in[4];
    const float* wk    = (const float*)d_in[5];
    const float* bk    = (const float*)d_in[6];
    const float* wv    = (const float*)d_in[7];
    const float* bv    = (const float*)d_in[8];
    const float* wp    = (const float*)d_in[9];
    const float* bp    = (const float*)d_in[10];
    float* out = (float*)d_out;

    fp16 *hthi, *htlo, *whi, *wlo, *qk, *v, *ohi, *olo, *a;
    float* ps;
    cudaGetSymbolAddress((void**)&hthi, g_ht_hi); cudaGetSymbolAddress((void**)&htlo, g_ht_lo);
    cudaGetSymbolAddress((void**)&whi, g_w_hi);   cudaGetSymbolAddress((void**)&wlo, g_w_lo);
    cudaGetSymbolAddress((void**)&qk, g_qk);
    cudaGetSymbolAddress((void**)&v, g_v);
    cudaGetSymbolAddress((void**)&ohi, g_o_hi);   cudaGetSymbolAddress((void**)&olo, g_o_lo);
    cudaGetSymbolAddress((void**)&a, g_a);
    cudaGetSymbolAddress((void**)&ps, g_s);

    const int SMEM_DYN = 3 * STG;    // 162 KB
    cudaFuncSetAttribute(gemm_hmma, cudaFuncAttributeMaxDynamicSharedMemorySize, SMEM_DYN);

    wconv_kernel<<<4 * (int)(WS / 256), 256>>>(wq, wk, wv, wp, whi, wlo);
    gn_kernel<<<64, 256>>>(x, gamma, beta, hthi, htlo);

    // QK fused (fp16x3): D[4096,1024] = hT @ [wq;wk]^T -> single fp16
    gemm_hmma<<<dim3(1024 / 256, NPX / 128, 2), 256, SMEM_DYN>>>(
        hthi, htlo, CCH, NH, whi, wlo, CCH, 0, CCH, 3,
        nullptr, qk, nullptr, nullptr, 1024, NQK, 1.0f, nullptr, bq, bk, nullptr);

    // V (fp16x3): [512,4096] -> single fp16, biasRow=bv
    gemm_hmma<<<dim3(NPX / 256, CCH / 128, 2), 256, SMEM_DYN>>>(
        whi + 2 * WS, wlo + 2 * WS, CCH, 0, hthi, htlo, CCH, NH, CCH, 3,
        nullptr, v, nullptr, nullptr, NPX, NH, 1.0f, bv, nullptr, nullptr, nullptr);

    // scores (single-pass fp16): fp32 [4096,4096]
    const float scale = 1.0f / sqrtf((float)CCH);
    gemm_hmma<<<dim3(NPX / 256, NPX / 128, 2), 256, SMEM_DYN>>>(
        qk, qk, 1024, NQK, qk + 512, qk + 512, 1024, NQK, CCH, 1,
        ps, nullptr, nullptr, nullptr, NPX, NN, scale, nullptr, nullptr, nullptr, nullptr);

    softmax_kernel<<<2 * NPX, 256>>>(ps, a);

    // O = attn @ V^T (single-pass fp16): [4096,512] -> hi/lo
    gemm_hmma<<<dim3(CCH / 256, NPX / 128, 2), 256, SMEM_DYN>>>(
        a, a, NPX, NN, v, v, NPX, NH, NPX, 1,
        nullptr, nullptr, ohi, olo, CCH, NH, 1.0f, nullptr, nullptr, nullptr, nullptr);

    // out = x + Wp @ O^T + bp (fp16x3): fp32 [512,4096]
    gemm_hmma<<<dim3(NPX / 256, CCH / 128, 2), 256, SMEM_DYN>>>(
        whi + 3 * WS, wlo + 3 * WS, CCH, 0, ohi, olo, CCH, NH, CCH, 3,
        out, nullptr, nullptr, nullptr, NPX, (size_t)CCH * NPX, 1.0f, bp, nullptr, nullptr, x);
}

// round 7
// speedup vs baseline: 6.9230x; 1.3898x over previous
#include <cuda_runtime.h>
#include <cuda_fp16.h>
#include <math.h>
#include <stdint.h>

#define CCH 512
#define NPX 4096
typedef __half fp16;

static const size_t NH  = (size_t)NPX * CCH;
static const size_t NN  = (size_t)NPX * NPX;
static const size_t NQK = (size_t)NPX * 1024;
#define WS ((size_t)CCH * CCH)

// ---------------- static scratch ----------------
__device__ fp16 g_ht[(size_t)2 * NPX * CCH];    // GN output [B][N][C]
__device__ fp16 g_w[(size_t)4 * CCH * CCH];     // wq,wk,wv,wp fp16
__device__ fp16 g_qk[(size_t)2 * NPX * 1024];   // Q cols 0-511, K cols 512-1023
__device__ fp16 g_v[(size_t)2 * CCH * NPX];     // [B][C][N]
__device__ fp16 g_o[(size_t)2 * NPX * CCH];     // [B][N][C]
__device__ fp16 g_s16[(size_t)2 * NPX * NPX];   // scores fp16
__device__ fp16 g_a[(size_t)2 * NPX * NPX];     // attn fp16

// ---------------- helpers ----------------
__device__ __forceinline__ uint32_t smem_u32(const void* p) {
    uint32_t a;
    asm("{ .reg .u64 t; cvta.to.shared.u64 t, %1; cvt.u32.u64 %0, t; }" : "=r"(a) : "l"(p));
    return a;
}
__device__ __forceinline__ uint32_t pack2(fp16 a, fp16 b) {
    __half2 t; t.x = a; t.y = b;
    return *reinterpret_cast<uint32_t*>(&t);
}
__device__ __forceinline__ void cp16(uint32_t s, const void* g) {
    asm volatile("cp.async.cg.shared.global [%0], [%1], 16;" :: "r"(s), "l"(g));
}
__device__ __forceinline__ void ldsm4(uint32_t* r, uint32_t addr) {
    asm volatile("ldmatrix.sync.aligned.m8n8.x4.shared.b16 {%0,%1,%2,%3}, [%4];"
        : "=r"(r[0]), "=r"(r[1]), "=r"(r[2]), "=r"(r[3]) : "r"(addr));
}
__device__ __forceinline__ void mma16816(float* d, const uint32_t* a, uint32_t b0, uint32_t b1) {
    asm volatile("mma.sync.aligned.m16n8k16.row.col.f32.f16.f16.f32 "
        "{%0,%1,%2,%3}, {%4,%5,%6,%7}, {%8,%9}, {%0,%1,%2,%3};"
        : "+f"(d[0]), "+f"(d[1]), "+f"(d[2]), "+f"(d[3])
        : "r"(a[0]), "r"(a[1]), "r"(a[2]), "r"(a[3]), "r"(b0), "r"(b1));
}

// ---------------- weight convert ----------------
__global__ void __launch_bounds__(256) wconv_kernel(const float* __restrict__ w0,
                                                    const float* __restrict__ w1,
                                                    const float* __restrict__ w2,
                                                    const float* __restrict__ w3,
                                                    fp16* __restrict__ o) {
    size_t i = (size_t)blockIdx.x * 256 + threadIdx.x;
    size_t which = i / WS, r = i - which * WS;
    const float* w = (which == 0) ? w0 : (which == 1) ? w1 : (which == 2) ? w2 : w3;
    o[i] = __float2half(w[r]);
}

// ---------------- GroupNorm + transpose -> fp16 [B][N][C] ----------------
__global__ void __launch_bounds__(256) gn_kernel(const float* __restrict__ x,
                                                 const float* __restrict__ gamma,
                                                 const float* __restrict__ beta,
                                                 fp16* __restrict__ ht) {
    int b = blockIdx.x >> 5;
    int g = blockIdx.x & 31;
    const size_t base = ((size_t)b * CCH + (size_t)g * 16) * NPX;
    const float4* xp = (const float4*)(x + base);
    const int TOT4 = 16 * NPX / 4;
    int tid = threadIdx.x;

    float s = 0.f, ss = 0.f;
    for (int i = tid; i < TOT4; i += 256) {
        float4 v = xp[i];
        s  += v.x + v.y + v.z + v.w;
        ss += v.x * v.x + v.y * v.y + v.z * v.z + v.w * v.w;
    }
    __shared__ float rs[8], rss[8];
    #pragma unroll
    for (int o = 16; o > 0; o >>= 1) {
        s  += __shfl_xor_sync(0xffffffffu, s, o);
        ss += __shfl_xor_sync(0xffffffffu, ss, o);
    }
    if ((tid & 31) == 0) { rs[tid >> 5] = s; rss[tid >> 5] = ss; }
    __syncthreads();
    float S = 0.f, SS = 0.f;
    #pragma unroll
    for (int w = 0; w < 8; w++) { S += rs[w]; SS += rss[w]; }
    const float inv_cnt = 1.0f / (float)(16 * NPX);
    float mean = S * inv_cnt;
    float var  = SS * inv_cnt - mean * mean;
    float rstd = rsqrtf(var + 1e-6f);

    __shared__ float sga[16], sbe[16];
    if (tid < 16) {
        int c = g * 16 + tid;
        float ga = gamma[c] * rstd;
        sga[tid] = ga;
        sbe[tid] = beta[c] - mean * ga;
    }
    __shared__ float xs[16][256];
    __syncthreads();

    for (int p0 = 0; p0 < NPX; p0 += 256) {
        #pragma unroll
        for (int c = 0; c < 16; c++) xs[c][tid] = x[base + (size_t)c * NPX + p0 + tid];
        __syncthreads();
        uint32_t hw[8];
        #pragma unroll
        for (int c2 = 0; c2 < 8; c2++) {
            float v0 = xs[2 * c2][tid]     * sga[2 * c2]     + sbe[2 * c2];
            float v1 = xs[2 * c2 + 1][tid] * sga[2 * c2 + 1] + sbe[2 * c2 + 1];
            hw[c2] = pack2(__float2half(v0), __float2half(v1));
        }
        size_t o = ((size_t)b * NPX + p0 + tid) * CCH + g * 16;
        ((uint4*)(g_ht + o))[0] = make_uint4(hw[0], hw[1], hw[2], hw[3]);
        ((uint4*)(g_ht + o))[1] = make_uint4(hw[4], hw[5], hw[6], hw[7]);
        __syncthreads();
    }
    (void)ht;
}

// ---------------- softmax fp16 -> fp16 ----------------
__global__ void __launch_bounds__(256) softmax_kernel(const fp16* __restrict__ S,
                                                      fp16* __restrict__ a) {
    size_t row = blockIdx.x;
    const __half2* p = (const __half2*)(S + row * NPX);
    int tid = threadIdx.x;
    float2 r[8];
    float m = -1e30f;
    #pragma unroll
    for (int i = 0; i < 8; i++) {
        __half2 h2 = p[tid + i * 256];
        r[i] = __half22float2(h2);
        m = fmaxf(m, fmaxf(r[i].x, r[i].y));
    }
    __shared__ float red[8];
    #pragma unroll
    for (int o = 16; o > 0; o >>= 1) m = fmaxf(m, __shfl_xor_sync(0xffffffffu, m, o));
    if ((tid & 31) == 0) red[tid >> 5] = m;
    __syncthreads();
    float bm = red[0];
    #pragma unroll
    for (int w = 1; w < 8; w++) bm = fmaxf(bm, red[w]);
    __syncthreads();
    float s = 0.f;
    #pragma unroll
    for (int i = 0; i < 8; i++) {
        r[i].x = __expf(r[i].x - bm); r[i].y = __expf(r[i].y - bm);
        s += r[i].x + r[i].y;
    }
    #pragma unroll
    for (int o = 16; o > 0; o >>= 1) s += __shfl_xor_sync(0xffffffffu, s, o);
    if ((tid & 31) == 0) red[tid >> 5] = s;
    __syncthreads();
    float bs = 0.f;
    #pragma unroll
    for (int w = 0; w < 8; w++) bs += red[w];
    float inv = 1.0f / bs;
    #pragma unroll
    for (int i = 0; i < 8; i++) {
        size_t idx = row * NPX + (tid + i * 256) * 2;
        *(uint32_t*)(a + idx) = pack2(__float2half(r[i].x * inv), __float2half(r[i].y * inv));
    }
}

// ---------------- fp16 HMMA GEMM (single pass) ----------------
// CTA tile 128x256, warp tile 64x64, BK=64, 3-stage cp.async.
#define ROWB  144
#define STG_A (128 * ROWB)
#define STG_B (256 * ROWB)
#define STG   (STG_A + STG_B)
__global__ void gemm_hmma(
    const fp16* __restrict__ A, int ldA, size_t strideA,
    const fp16* __restrict__ B, int ldB, size_t strideB,
    int K,
    float* __restrict__ outF32, fp16* __restrict__ outH,
    int ldD, size_t strideD,
    float scale,
    const float* __restrict__ biasRow,
    const float* __restrict__ biasCol, const float* __restrict__ biasCol2,
    const float* __restrict__ resid)
{
    extern __shared__ char smemraw[];
    int tid = threadIdx.x, wid = tid >> 5, lane = tid & 31;
    int m0 = blockIdx.y * 128, n0 = blockIdx.x * 256, bz = blockIdx.z;
    A += (size_t)bz * strideA;
    B += (size_t)bz * strideB;

    uint32_t base = smem_u32(smemraw);
    int wm = wid & 1, wn = wid >> 1;

    const int nch = K >> 6;

    float acc[4][8][4];
    #pragma unroll
    for (int a = 0; a < 4; a++)
        #pragma unroll
        for (int b = 0; b < 8; b++)
            #pragma unroll
            for (int c = 0; c < 4; c++) acc[a][b][c] = 0.f;

    auto load_chunk = [&](int i) {
        int st = i % 3;
        size_t kb = (size_t)i * 64;
        uint32_t sa = base + st * STG;
        uint32_t sb = sa + STG_A;
        #pragma unroll
        for (int r = 0; r < 4; r++) {
            int u = tid + r * 256;
            int row = u >> 3, cs = u & 7;
            cp16(sa + (uint32_t)(row * ROWB + cs * 16),
                 A + (size_t)(m0 + row) * ldA + kb + cs * 8);
        }
        #pragma unroll
        for (int r = 0; r < 8; r++) {
            int u = tid + r * 256;
            int row = u >> 3, cs = u & 7;
            cp16(sb + (uint32_t)(row * ROWB + cs * 16),
                 B + (size_t)(n0 + row) * ldB + kb + cs * 8);
        }
    };

    load_chunk(0);
    asm volatile("cp.async.commit_group;" ::: "memory");
    if (nch > 1) load_chunk(1);
    asm volatile("cp.async.commit_group;" ::: "memory");

    uint32_t a_off[4], b_off[4];
    #pragma unroll
    for (int mi = 0; mi < 4; mi++) {
        int row = wm * 64 + mi * 16 + (lane & 15);
        a_off[mi] = (uint32_t)(row * ROWB + ((lane >> 4) * 8) * 2);
    }
    #pragma unroll
    for (int nb = 0; nb < 4; nb++) {
        int row = wn * 64 + nb * 16 + ((lane >> 4) << 3) + (lane & 7);
        b_off[nb] = (uint32_t)(row * ROWB + ((((lane >> 3) & 1) << 3)) * 2);
    }

    for (int i = 0; i < nch; i++) {
        if (i < nch - 1) asm volatile("cp.async.wait_group 1;" ::: "memory");
        else             asm volatile("cp.async.wait_group 0;" ::: "memory");
        __syncthreads();
        if (i + 2 < nch) {
            load_chunk(i + 2);
            asm volatile("cp.async.commit_group;" ::: "memory");
        }

        uint32_t sa = base + (i % 3) * STG;
        uint32_t sb = sa + STG_A;

        uint32_t afr[2][4][4], bfr[2][4][4];
        #pragma unroll
        for (int mi = 0; mi < 4; mi++) ldsm4(afr[0][mi], sa + a_off[mi]);
        #pragma unroll
        for (int nb = 0; nb < 4; nb++) ldsm4(bfr[0][nb], sb + b_off[nb]);

        #pragma unroll
        for (int kk = 0; kk < 4; kk++) {
            int cur = kk & 1, nxt = cur ^ 1;
            if (kk < 3) {
                uint32_t ko = (uint32_t)((kk + 1) * 32);
                #pragma unroll
                for (int mi = 0; mi < 4; mi++) ldsm4(afr[nxt][mi], sa + a_off[mi] + ko);
                #pragma unroll
                for (int nb = 0; nb < 4; nb++) ldsm4(bfr[nxt][nb], sb + b_off[nb] + ko);
            }
            #pragma unroll
            for (int mi = 0; mi < 4; mi++)
                #pragma unroll
                for (int ni = 0; ni < 8; ni++)
                    mma16816(acc[mi][ni], afr[cur][mi],
                             bfr[cur][ni >> 1][(ni & 1) * 2], bfr[cur][ni >> 1][(ni & 1) * 2 + 1]);
        }
    }

    // ---------------- epilogue ----------------
    int r4 = lane >> 2;
    int c2 = lane & 3;
    float* of = outF32 ? outF32 + (size_t)bz * strideD : nullptr;
    fp16* oh  = outH   ? outH   + (size_t)bz * strideD : nullptr;
    const float* rp = resid ? resid + (size_t)bz * strideD : nullptr;

    #pragma unroll
    for (int mi = 0; mi < 4; mi++) {
        #pragma unroll
        for (int half = 0; half < 2; half++) {
            int m = m0 + wm * 64 + mi * 16 + half * 8 + r4;
            float brow = biasRow ? biasRow[m] : 0.f;
            #pragma unroll
            for (int ni = 0; ni < 8; ni++) {
                int n = n0 + wn * 64 + ni * 8 + c2 * 2;
                float v0 = acc[mi][ni][half * 2 + 0] * scale + brow;
                float v1 = acc[mi][ni][half * 2 + 1] * scale + brow;
                if (biasCol) {
                    const float* bc = (biasCol2 && n >= 512) ? biasCol2 - 512 : biasCol;
                    v0 += bc[n]; v1 += bc[n + 1];
                }
                size_t off = (size_t)m * ldD + n;
                if (rp) {
                    float2 q = *(const float2*)(rp + off);
                    v0 += q.x; v1 += q.y;
                }
                if (of) *(float2*)(of + off) = make_float2(v0, v1);
                if (oh) *(uint32_t*)(oh + off) = pack2(__float2half(v0), __float2half(v1));
            }
        }
    }
}

// ---------------- launch ----------------
extern "C" void kernel_launch(void* const* d_in, const int* in_sizes, int n_in,
                              void* d_out, int out_size) {
    const float* x     = (const float*)d_in[0];
    const float* gamma = (const float*)d_in[1];
    const float* beta  = (const float*)d_in[2];
    const float* wq    = (const float*)d_in[3];
    const float* bq    = (const float*)d_in[4];
    const float* wk    = (const float*)d_in[5];
    const float* bk    = (const float*)d_in[6];
    const float* wv    = (const float*)d_in[7];
    const float* bv    = (const float*)d_in[8];
    const float* wp    = (const float*)d_in[9];
    const float* bp    = (const float*)d_in[10];
    float* out = (float*)d_out;

    fp16 *ht, *w, *qk, *v, *o, *s16, *a;
    cudaGetSymbolAddress((void**)&ht, g_ht);
    cudaGetSymbolAddress((void**)&w, g_w);
    cudaGetSymbolAddress((void**)&qk, g_qk);
    cudaGetSymbolAddress((void**)&v, g_v);
    cudaGetSymbolAddress((void**)&o, g_o);
    cudaGetSymbolAddress((void**)&s16, g_s16);
    cudaGetSymbolAddress((void**)&a, g_a);

    const int SMEM_DYN = 3 * STG;    // 162 KB
    cudaFuncSetAttribute(gemm_hmma, cudaFuncAttributeMaxDynamicSharedMemorySize, SMEM_DYN);

    wconv_kernel<<<4 * (int)(WS / 256), 256>>>(wq, wk, wv, wp, w);
    gn_kernel<<<64, 256>>>(x, gamma, beta, ht);

    // QK fused: D[4096,1024] = hT @ [wq;wk]^T -> fp16
    gemm_hmma<<<dim3(1024 / 256, NPX / 128, 2), 256, SMEM_DYN>>>(
        ht, CCH, NH, w, CCH, 0, CCH,
        nullptr, qk, 1024, NQK, 1.0f, nullptr, bq, bk, nullptr);

    // V: [512,4096] -> fp16, biasRow=bv
    gemm_hmma<<<dim3(NPX / 256, CCH / 128, 2), 256, SMEM_DYN>>>(
        w + 2 * WS, CCH, 0, ht, CCH, NH, CCH,
        nullptr, v, NPX, NH, 1.0f, bv, nullptr, nullptr, nullptr);

    // scores: fp16 [4096,4096]
    const float scale = 1.0f / sqrtf((float)CCH);
    gemm_hmma<<<dim3(NPX / 256, NPX / 128, 2), 256, SMEM_DYN>>>(
        qk, 1024, NQK, qk + 512, 1024, NQK, CCH,
        nullptr, s16, NPX, NN, scale, nullptr, nullptr, nullptr, nullptr);

    softmax_kernel<<<2 * NPX, 256>>>(s16, a);

    // O = attn @ V^T: [4096,512] -> fp16
    gemm_hmma<<<dim3(CCH / 256, NPX / 128, 2), 256, SMEM_DYN>>>(
        a, NPX, NN, v, NPX, NH, NPX,
        nullptr, o, CCH, NH, 1.0f, nullptr, nullptr, nullptr, nullptr);

    // out = x + Wp @ O^T + bp: fp32 [512,4096]
    gemm_hmma<<<dim3(NPX / 256, CCH / 128, 2), 256, SMEM_DYN>>>(
        w + 3 * WS, CCH, 0, o, CCH, NH, CCH,
        out, nullptr, NPX, (size_t)CCH * NPX, 1.0f, bp, nullptr, nullptr, x);
}